// round 5
// baseline (speedup 1.0000x reference)
#include <cuda_runtime.h>
#include <cstdint>

// ---------------------------------------------------------------------------
// Problem constants
// ---------------------------------------------------------------------------
#define BATCH 256
#define SEQ   64
#define DIM   1024
#define NHEAD 32
#define DHEAD 32
#define NEXP  4
#define HID   1536
#define CAP   32
#define NTOK  (BATCH*SEQ)            // 16384
#define EROWS (BATCH*CAP)            // 8192 rows per expert

// ---------------------------------------------------------------------------
// Scratch (device globals; no allocation allowed)
// ---------------------------------------------------------------------------
__device__ float g_q  [NTOK*DIM];
__device__ float g_k  [NTOK*DIM];
__device__ float g_v  [NTOK*DIM];
__device__ float g_ctx[NTOK*DIM];
__device__ float g_a  [NTOK*DIM];
__device__ float g_x1 [NTOK*DIM];
__device__ float g_pos[SEQ*DIM];
__device__ float g_raw[NTOK*NEXP];
__device__ int   g_assign[NEXP*EROWS];
__device__ int   g_sE1[NTOK]; __device__ int g_sP1[NTOK]; __device__ float g_sG1[NTOK];
__device__ int   g_sE2[NTOK]; __device__ int g_sP2[NTOK]; __device__ float g_sG2[NTOK];
__device__ float g_ei [NEXP*EROWS*DIM];
__device__ float g_hid[NEXP*EROWS*HID];
__device__ float g_eo [NEXP*EROWS*DIM];
__device__ float g_loss[1];

// ---------------------------------------------------------------------------
// Block reduce helper
// ---------------------------------------------------------------------------
__device__ __forceinline__ float blockReduceSum(float v) {
    __shared__ float sh[8];
    __shared__ float tot;
    int lane = threadIdx.x & 31, wid = threadIdx.x >> 5;
    #pragma unroll
    for (int o = 16; o; o >>= 1) v += __shfl_down_sync(0xFFFFFFFFu, v, o);
    if (lane == 0) sh[wid] = v;
    __syncthreads();
    if (wid == 0) {
        v = (lane < 8) ? sh[lane] : 0.f;
        #pragma unroll
        for (int o = 4; o; o >>= 1) v += __shfl_down_sync(0xFFFFFFFFu, v, o);
        if (lane == 0) tot = v;
    }
    __syncthreads();
    return tot;
}

// ---------------------------------------------------------------------------
// Threefry2x32, PARTITIONABLE path (JAX >= 0.4.36 default:
// jax_threefry_partitionable=True).
// Per element j: block input (x0, x1) = (counts_hi, counts_lo) = (0, j),
// key = (0, 1234); ks2 = 0 ^ 1234 ^ 0x1BD11BDA = 0x1BD11F08.
// 32-bit output bits = x0_final ^ x1_final.
// uniform = bitcast((bits>>9)|0x3f800000) - 1
// ---------------------------------------------------------------------------
#define TF_ROT(x0, x1, r)  { x0 += x1; x1 = ((x1 << (r)) | (x1 >> (32 - (r)))); x1 ^= x0; }
__device__ float jax_uniform_token(int j) {
    const unsigned KS0 = 0u;
    const unsigned KS1 = 1234u;
    const unsigned KS2 = 0x1BD11F08u;   // 0 ^ 1234 ^ 0x1BD11BDA
    unsigned x0 = 0u;                   // counts_hi (size 16384 < 2^32)
    unsigned x1 = (unsigned)j;          // counts_lo
    // initial key injection
    x0 += KS0; x1 += KS1;
    // group 1: rotations 13,15,26,6
    TF_ROT(x0, x1, 13) TF_ROT(x0, x1, 15) TF_ROT(x0, x1, 26) TF_ROT(x0, x1, 6)
    x0 += KS1; x1 += KS2 + 1u;
    // group 2: rotations 17,29,16,24
    TF_ROT(x0, x1, 17) TF_ROT(x0, x1, 29) TF_ROT(x0, x1, 16) TF_ROT(x0, x1, 24)
    x0 += KS2; x1 += KS0 + 2u;
    // group 3: rotations 13,15,26,6
    TF_ROT(x0, x1, 13) TF_ROT(x0, x1, 15) TF_ROT(x0, x1, 26) TF_ROT(x0, x1, 6)
    x0 += KS0; x1 += KS1 + 3u;
    // group 4: rotations 17,29,16,24
    TF_ROT(x0, x1, 17) TF_ROT(x0, x1, 29) TF_ROT(x0, x1, 16) TF_ROT(x0, x1, 24)
    x0 += KS1; x1 += KS2 + 4u;
    // group 5: rotations 13,15,26,6
    TF_ROT(x0, x1, 13) TF_ROT(x0, x1, 15) TF_ROT(x0, x1, 26) TF_ROT(x0, x1, 6)
    x0 += KS2; x1 += KS0 + 5u;
    unsigned bits = x0 ^ x1;            // partitionable 32-bit output
    unsigned f = (bits >> 9) | 0x3f800000u;
    return __uint_as_float(f) - 1.0f;
}

// ---------------------------------------------------------------------------
// SGEMM: C[M,N] = A[M,K] @ B[K,N] (+bias) (relu). 128x128x8 tile, 256 thr, 8x8
// Exact fp32.
// ---------------------------------------------------------------------------
template<bool BIAS, bool RELU>
__global__ __launch_bounds__(256, 2)
void sgemm_kernel(const float* __restrict__ A, const float* __restrict__ B,
                  const float* __restrict__ bias, float* __restrict__ C,
                  int M, int N, int K) {
    __shared__ float As[8][128];
    __shared__ float Bs[8][128];
    const int tid = threadIdx.x;
    const int tx = tid & 15, ty = tid >> 4;
    const int row0 = blockIdx.y * 128, col0 = blockIdx.x * 128;
    const int a_r = tid >> 1, a_c = (tid & 1) * 4;
    const int b_r = tid >> 5, b_c = (tid & 31) * 4;
    float acc[8][8];
    #pragma unroll
    for (int i = 0; i < 8; i++)
        #pragma unroll
        for (int j = 0; j < 8; j++) acc[i][j] = 0.f;
    const bool aok = (row0 + a_r) < M;
    const float* Aptr = A + (size_t)(row0 + a_r) * K + a_c;
    const float* Bptr = B + (size_t)b_r * N + col0 + b_c;
    for (int k0 = 0; k0 < K; k0 += 8) {
        float4 av = aok ? *(const float4*)(Aptr + k0) : make_float4(0.f, 0.f, 0.f, 0.f);
        As[a_c + 0][a_r] = av.x; As[a_c + 1][a_r] = av.y;
        As[a_c + 2][a_r] = av.z; As[a_c + 3][a_r] = av.w;
        *(float4*)&Bs[b_r][b_c] = *(const float4*)(Bptr + (size_t)k0 * N);
        __syncthreads();
        #pragma unroll
        for (int kk = 0; kk < 8; kk++) {
            float ar[8], br[8];
            *(float4*)&ar[0] = *(const float4*)&As[kk][ty * 4];
            *(float4*)&ar[4] = *(const float4*)&As[kk][64 + ty * 4];
            *(float4*)&br[0] = *(const float4*)&Bs[kk][tx * 4];
            *(float4*)&br[4] = *(const float4*)&Bs[kk][64 + tx * 4];
            #pragma unroll
            for (int i = 0; i < 8; i++)
                #pragma unroll
                for (int j = 0; j < 8; j++) acc[i][j] += ar[i] * br[j];
        }
        __syncthreads();
    }
    #pragma unroll
    for (int ig = 0; ig < 2; ig++) {
        #pragma unroll
        for (int ii = 0; ii < 4; ii++) {
            int r = row0 + ig * 64 + ty * 4 + ii;
            if (r >= M) continue;
            #pragma unroll
            for (int jg = 0; jg < 2; jg++) {
                int c = col0 + jg * 64 + tx * 4;
                float4 o;
                o.x = acc[ig * 4 + ii][jg * 4 + 0];
                o.y = acc[ig * 4 + ii][jg * 4 + 1];
                o.z = acc[ig * 4 + ii][jg * 4 + 2];
                o.w = acc[ig * 4 + ii][jg * 4 + 3];
                if (BIAS) {
                    o.x += bias[c];     o.y += bias[c + 1];
                    o.z += bias[c + 2]; o.w += bias[c + 3];
                }
                if (RELU) {
                    o.x = fmaxf(o.x, 0.f); o.y = fmaxf(o.y, 0.f);
                    o.z = fmaxf(o.z, 0.f); o.w = fmaxf(o.w, 0.f);
                }
                *(float4*)&C[(size_t)r * N + c] = o;
            }
        }
    }
}

// ---------------------------------------------------------------------------
// Init scratch (assign = -1, loss = 0)
// ---------------------------------------------------------------------------
__global__ void init_kernel() {
    int i = blockIdx.x * blockDim.x + threadIdx.x;
    if (i < NEXP * EROWS) g_assign[i] = -1;
    if (i == 0) g_loss[0] = 0.f;
}

// ---------------------------------------------------------------------------
// Fused rel-pos attention: one block per (b,h). 256 threads, 48KB static smem.
// ---------------------------------------------------------------------------
__global__ __launch_bounds__(256)
void attn_kernel(const float* __restrict__ u_bias, const float* __restrict__ v_bias) {
    __shared__ float qs[SEQ * DHEAD];
    __shared__ float ks[SEQ * DHEAD];
    __shared__ float vs[SEQ * DHEAD];
    __shared__ float ps[SEQ * DHEAD];
    __shared__ float pr[SEQ * SEQ];     // reused: pos scores -> shifted -> attn
    const int b = blockIdx.x >> 5;
    const int h = blockIdx.x & 31;
    const int tid = threadIdx.x;

    #pragma unroll
    for (int t = 0; t < 8; t++) {
        int idx = tid + t * 256;
        int s = idx >> 5, d = idx & 31;
        size_t g = ((size_t)((b * SEQ + s) * NHEAD + h)) * DHEAD + d;
        qs[idx] = g_q[g]; ks[idx] = g_k[g]; vs[idx] = g_v[g];
        ps[idx] = g_pos[(size_t)(s * NHEAD + h) * DHEAD + d];
    }
    __syncthreads();

    const int i  = tid >> 2;
    const int j0 = (tid & 3) * 16;
    float qd[32];

    // pos scores: (q + v_bias) @ pos^T
    #pragma unroll
    for (int d = 0; d < 32; d++) qd[d] = qs[i * 32 + d] + __ldg(&v_bias[h * 32 + d]);
    #pragma unroll
    for (int jj = 0; jj < 16; jj++) {
        int j = j0 + jj;
        float a = 0.f;
        #pragma unroll
        for (int d = 0; d < 32; d++) a += qd[d] * ps[j * 32 + d];
        pr[i * 64 + j] = a;
    }
    __syncthreads();

    // Transformer-XL relative shift (into registers, then write back)
    float sh[16];
    #pragma unroll
    for (int jj = 0; jj < 16; jj++) {
        int c = j0 + jj;
        int f = (i + 1) * 64 + c;
        int ii = f / 65;
        int jp = f - ii * 65;
        sh[jj] = (jp == 0) ? 0.f : pr[ii * 64 + (jp - 1)];
    }
    __syncthreads();
    #pragma unroll
    for (int jj = 0; jj < 16; jj++) pr[i * 64 + j0 + jj] = sh[jj];
    __syncthreads();

    // content scores: (q + u_bias) @ k^T ; combine + scale by 1/sqrt(D)=1/32
    #pragma unroll
    for (int d = 0; d < 32; d++) qd[d] = qs[i * 32 + d] + __ldg(&u_bias[h * 32 + d]);
    #pragma unroll
    for (int jj = 0; jj < 16; jj++) {
        int j = j0 + jj;
        float a = 0.f;
        #pragma unroll
        for (int d = 0; d < 32; d++) a += qd[d] * ks[j * 32 + d];
        pr[i * 64 + j] = (a + pr[i * 64 + j]) * 0.03125f;
    }
    // softmax over j, row i handled by 4 consecutive threads (warp-aligned)
    float m = -1e30f;
    #pragma unroll
    for (int jj = 0; jj < 16; jj++) m = fmaxf(m, pr[i * 64 + j0 + jj]);
    m = fmaxf(m, __shfl_xor_sync(0xFFFFFFFFu, m, 1));
    m = fmaxf(m, __shfl_xor_sync(0xFFFFFFFFu, m, 2));
    float ex[16], ssum = 0.f;
    #pragma unroll
    for (int jj = 0; jj < 16; jj++) { ex[jj] = expf(pr[i * 64 + j0 + jj] - m); ssum += ex[jj]; }
    ssum += __shfl_xor_sync(0xFFFFFFFFu, ssum, 1);
    ssum += __shfl_xor_sync(0xFFFFFFFFu, ssum, 2);
    float inv = 1.0f / ssum;
    #pragma unroll
    for (int jj = 0; jj < 16; jj++) pr[i * 64 + j0 + jj] = ex[jj] * inv;
    __syncthreads();

    // ctx = attn @ v : thread computes 8 of 64x32 outputs
    const int i2 = tid >> 2;
    const int d0 = (tid & 3) * 8;
    float o[8] = {0.f, 0.f, 0.f, 0.f, 0.f, 0.f, 0.f, 0.f};
    for (int j = 0; j < 64; j++) {
        float aw = pr[i2 * 64 + j];
        #pragma unroll
        for (int dd = 0; dd < 8; dd++) o[dd] += aw * vs[j * 32 + d0 + dd];
    }
    size_t gbase = ((size_t)((b * SEQ + i2) * NHEAD + h)) * DHEAD + d0;
    #pragma unroll
    for (int dd = 0; dd < 8; dd++) g_ctx[gbase + dd] = o[dd];
}

// ---------------------------------------------------------------------------
// LN1: x1 = LayerNorm(g_a + x)
// ---------------------------------------------------------------------------
__global__ __launch_bounds__(256)
void ln1_kernel(const float* __restrict__ x, const float* __restrict__ gma,
                const float* __restrict__ bta) {
    int row = blockIdx.x, tid = threadIdx.x;
    const float* pa = g_a + (size_t)row * DIM;
    const float* pr = x   + (size_t)row * DIM;
    float vals[4], s = 0.f;
    #pragma unroll
    for (int t = 0; t < 4; t++) {
        int c = tid + t * 256;
        float v = pa[c] + pr[c];
        vals[t] = v; s += v;
    }
    s = blockReduceSum(s);
    float mu = s * (1.f / DIM);
    float vsum = 0.f;
    #pragma unroll
    for (int t = 0; t < 4; t++) { float d = vals[t] - mu; vsum += d * d; }
    vsum = blockReduceSum(vsum);
    float rstd = rsqrtf(vsum * (1.f / DIM) + 1e-5f);
    #pragma unroll
    for (int t = 0; t < 4; t++) {
        int c = tid + t * 256;
        g_x1[(size_t)row * DIM + c] = (vals[t] - mu) * rstd * gma[c] + bta[c];
    }
}

// ---------------------------------------------------------------------------
// Gating: raw = softmax(x1 @ w_gating) per token (one warp per token)
// ---------------------------------------------------------------------------
__global__ __launch_bounds__(256)
void gating_kernel(const float* __restrict__ wg) {
    int warp = (blockIdx.x * blockDim.x + threadIdx.x) >> 5;
    int lane = threadIdx.x & 31;
    if (warp >= NTOK) return;
    const float* xr = g_x1 + (size_t)warp * DIM;
    float a0 = 0.f, a1 = 0.f, a2 = 0.f, a3 = 0.f;
    for (int d = lane; d < DIM; d += 32) {
        float xv = xr[d];
        float4 w = ((const float4*)wg)[d];
        a0 += xv * w.x; a1 += xv * w.y; a2 += xv * w.z; a3 += xv * w.w;
    }
    #pragma unroll
    for (int o = 16; o; o >>= 1) {
        a0 += __shfl_down_sync(0xFFFFFFFFu, a0, o);
        a1 += __shfl_down_sync(0xFFFFFFFFu, a1, o);
        a2 += __shfl_down_sync(0xFFFFFFFFu, a2, o);
        a3 += __shfl_down_sync(0xFFFFFFFFu, a3, o);
    }
    if (lane == 0) {
        float m = fmaxf(fmaxf(a0, a1), fmaxf(a2, a3));
        float e0 = expf(a0 - m), e1 = expf(a1 - m), e2 = expf(a2 - m), e3 = expf(a3 - m);
        float s = e0 + e1 + e2 + e3;
        g_raw[warp * 4 + 0] = e0 / s;
        g_raw[warp * 4 + 1] = e1 / s;
        g_raw[warp * 4 + 2] = e2 / s;
        g_raw[warp * 4 + 3] = e3 / s;
    }
}

// ---------------------------------------------------------------------------
// Routing: serial per batch (matches JAX cumsum/capacity semantics exactly)
// ---------------------------------------------------------------------------
__global__ void routing_kernel() {
    if (threadIdx.x != 0) return;
    int b = blockIdx.x;
    int cnt1[4] = {0, 0, 0, 0};
    float dens[4] = {0.f, 0.f, 0.f, 0.f};
    float proxy[4] = {0.f, 0.f, 0.f, 0.f};
    int e2a[64]; float g2a[64]; bool k2a[64];

    for (int n = 0; n < SEQ; n++) {
        int tok = b * SEQ + n;
        float rr[4];
        #pragma unroll
        for (int e = 0; e < 4; e++) { rr[e] = g_raw[tok * 4 + e]; proxy[e] += rr[e]; }
        int e1 = 0; float g1 = rr[0];
        #pragma unroll
        for (int e = 1; e < 4; e++) if (rr[e] > g1) { g1 = rr[e]; e1 = e; }
        int e2 = -1; float g2 = -1.f;
        #pragma unroll
        for (int e = 0; e < 4; e++) {
            if (e == e1) continue;
            if (rr[e] > g2) { g2 = rr[e]; e2 = e; }
        }
        dens[e1] += 1.f;
        float denom = g1 + g2 + 1e-9f;
        float g1n = g1 / denom, g2n = g2 / denom;
        int p1 = cnt1[e1]++;
        g_sE1[tok] = e1;
        if (p1 < CAP) {
            g_sP1[tok] = p1; g_sG1[tok] = g1n;
            g_assign[(e1 * BATCH + b) * CAP + p1] = tok;
        } else {
            g_sP1[tok] = -1; g_sG1[tok] = 0.f;
        }
        float u = jax_uniform_token(tok);
        k2a[n] = (u < g2n / 0.2f);
        e2a[n] = e2; g2a[n] = g2n;
    }
    int c1c[4];
    #pragma unroll
    for (int e = 0; e < 4; e++) c1c[e] = cnt1[e] < CAP ? cnt1[e] : CAP;
    int cnt2[4] = {0, 0, 0, 0};
    for (int n = 0; n < SEQ; n++) {
        int tok = b * SEQ + n;
        g_sE2[tok] = e2a[n];
        g_sP2[tok] = -1; g_sG2[tok] = 0.f;
        if (k2a[n]) {
            int e2 = e2a[n];
            int p2 = cnt2[e2] + c1c[e2];
            cnt2[e2]++;
            if (p2 < CAP) {
                g_sP2[tok] = p2; g_sG2[tok] = g2a[n];
                g_assign[(e2 * BATCH + b) * CAP + p2] = tok;
            }
        }
    }
    float part = 0.f;
    #pragma unroll
    for (int e = 0; e < 4; e++) part += (proxy[e] * (1.f / SEQ)) * (dens[e] * (1.f / SEQ));
    atomicAdd(&g_loss[0], part);
}

// ---------------------------------------------------------------------------
// Gather dispatched tokens into expert input rows (zero for empty slots)
// ---------------------------------------------------------------------------
__global__ __launch_bounds__(256)
void gather_kernel() {
    int row = blockIdx.x;               // 0 .. NEXP*EROWS-1
    int tok = g_assign[row];
    float4* dst = ((float4*)g_ei) + (size_t)row * 256;
    if (tok >= 0) {
        const float4* src = ((const float4*)g_x1) + (size_t)tok * 256;
        dst[threadIdx.x] = src[threadIdx.x];
    } else {
        dst[threadIdx.x] = make_float4(0.f, 0.f, 0.f, 0.f);
    }
}

// ---------------------------------------------------------------------------
// Combine expert outputs + residual + LN2 -> d_out ; write loss scalar
// ---------------------------------------------------------------------------
__global__ __launch_bounds__(256)
void combine_ln2_kernel(const float* __restrict__ gma, const float* __restrict__ bta,
                        float* __restrict__ out, int out_size) {
    int tok = blockIdx.x, tid = threadIdx.x;
    int b = tok >> 6;
    int p1 = g_sP1[tok], p2 = g_sP2[tok];
    float g1 = g_sG1[tok], g2 = g_sG2[tok];
    const float* r1 = (p1 >= 0) ? g_eo + ((size_t)g_sE1[tok] * EROWS + b * CAP + p1) * DIM : nullptr;
    const float* r2 = (p2 >= 0) ? g_eo + ((size_t)g_sE2[tok] * EROWS + b * CAP + p2) * DIM : nullptr;
    const float* xr = g_x1 + (size_t)tok * DIM;
    float vals[4], s = 0.f;
    #pragma unroll
    for (int t = 0; t < 4; t++) {
        int c = tid + t * 256;
        float y = 0.f;
        if (r1) y += g1 * r1[c];
        if (r2) y += g2 * r2[c];
        float v = y + xr[c];
        vals[t] = v; s += v;
    }
    s = blockReduceSum(s);
    float mu = s * (1.f / DIM);
    float vsum = 0.f;
    #pragma unroll
    for (int t = 0; t < 4; t++) { float d = vals[t] - mu; vsum += d * d; }
    vsum = blockReduceSum(vsum);
    float rstd = rsqrtf(vsum * (1.f / DIM) + 1e-5f);
    #pragma unroll
    for (int t = 0; t < 4; t++) {
        int c = tid + t * 256;
        out[(size_t)tok * DIM + c] = (vals[t] - mu) * rstd * gma[c] + bta[c];
    }
    if (tok == 0 && tid == 0 && out_size > NTOK * DIM) {
        // loss = sum_b(sum_e proxy*dens) / (B*E) * E*E * 0.01
        out[(size_t)NTOK * DIM] = g_loss[0] * ((float)(NEXP * NEXP) * 0.01f / (float)(BATCH * NEXP));
    }
}

// ---------------------------------------------------------------------------
// Host side
// ---------------------------------------------------------------------------
static void launch_gemm(const float* A, const float* B, const float* bias, float* C,
                        int M, int N, int K, bool biasF, bool reluF) {
    dim3 grid(N / 128, (M + 127) / 128);
    if (biasF)      sgemm_kernel<true,  false><<<grid, 256>>>(A, B, bias, C, M, N, K);
    else if (reluF) sgemm_kernel<false, true ><<<grid, 256>>>(A, B, bias, C, M, N, K);
    else            sgemm_kernel<false, false><<<grid, 256>>>(A, B, bias, C, M, N, K);
}

extern "C" void kernel_launch(void* const* d_in, const int* in_sizes, int n_in,
                              void* d_out, int out_size) {
    const float* x       = (const float*)d_in[0];
    const float* pos_enc = (const float*)d_in[1];
    const float* Wq      = (const float*)d_in[2];
    const float* bq      = (const float*)d_in[3];
    const float* Wk      = (const float*)d_in[4];
    const float* bk      = (const float*)d_in[5];
    const float* Wv      = (const float*)d_in[6];
    const float* bv      = (const float*)d_in[7];
    const float* Wpos    = (const float*)d_in[8];
    const float* u_bias  = (const float*)d_in[9];
    const float* v_bias  = (const float*)d_in[10];
    const float* Wo      = (const float*)d_in[11];
    const float* bo      = (const float*)d_in[12];
    const float* ln1_g   = (const float*)d_in[13];
    const float* ln1_b   = (const float*)d_in[14];
    const float* ln2_g   = (const float*)d_in[15];
    const float* ln2_b   = (const float*)d_in[16];
    const float* wg      = (const float*)d_in[17];
    const float* w1      = (const float*)d_in[18];
    const float* w2      = (const float*)d_in[19];
    float* out = (float*)d_out;

    float *q, *k, *v, *ctx, *a, *pos, *ei, *hid, *eo;
    cudaGetSymbolAddress((void**)&q,   g_q);
    cudaGetSymbolAddress((void**)&k,   g_k);
    cudaGetSymbolAddress((void**)&v,   g_v);
    cudaGetSymbolAddress((void**)&ctx, g_ctx);
    cudaGetSymbolAddress((void**)&a,   g_a);
    cudaGetSymbolAddress((void**)&pos, g_pos);
    cudaGetSymbolAddress((void**)&ei,  g_ei);
    cudaGetSymbolAddress((void**)&hid, g_hid);
    cudaGetSymbolAddress((void**)&eo,  g_eo);

    init_kernel<<<128, 256>>>();

    // Projections
    launch_gemm(x, Wq, bq, q, NTOK, DIM, DIM, true, false);
    launch_gemm(x, Wk, bk, k, NTOK, DIM, DIM, true, false);
    launch_gemm(x, Wv, bv, v, NTOK, DIM, DIM, true, false);
    launch_gemm(pos_enc, Wpos, nullptr, pos, SEQ, DIM, DIM, false, false);

    // Fused rel-pos attention core
    attn_kernel<<<BATCH * NHEAD, 256>>>(u_bias, v_bias);

    // Output projection + residual LN
    launch_gemm(ctx, Wo, bo, a, NTOK, DIM, DIM, true, false);
    ln1_kernel<<<NTOK, 256>>>(x, ln1_g, ln1_b);

    // MoE
    gating_kernel<<<(NTOK * 32 + 255) / 256, 256>>>(wg);
    routing_kernel<<<BATCH, 32>>>();
    gather_kernel<<<NEXP * EROWS, 256>>>();
    for (int e = 0; e < NEXP; e++) {
        launch_gemm(ei + (size_t)e * EROWS * DIM, w1 + (size_t)e * DIM * HID, nullptr,
                    hid + (size_t)e * EROWS * HID, EROWS, HID, DIM, false, true);
    }
    for (int e = 0; e < NEXP; e++) {
        launch_gemm(hid + (size_t)e * EROWS * HID, w2 + (size_t)e * HID * DIM, nullptr,
                    eo + (size_t)e * EROWS * DIM, EROWS, DIM, HID, false, false);
    }

    // Combine + residual + LN2 + loss
    combine_ln2_kernel<<<NTOK, 256>>>(ln2_g, ln2_b, out, out_size);
}

// round 6
// speedup vs baseline: 2.4494x; 2.4494x over previous
#include <cuda_runtime.h>
#include <cstdint>

// ---------------------------------------------------------------------------
// Problem constants
// ---------------------------------------------------------------------------
#define BATCH 256
#define SEQ   64
#define DIM   1024
#define NHEAD 32
#define DHEAD 32
#define NEXP  4
#define HID   1536
#define CAP   32
#define NTOK  (BATCH*SEQ)            // 16384
#define EROWS (BATCH*CAP)            // 8192 rows per expert

// ---------------------------------------------------------------------------
// Scratch (device globals; no allocation allowed)
// ---------------------------------------------------------------------------
__device__ float g_q  [NTOK*DIM];
__device__ float g_k  [NTOK*DIM];
__device__ float g_v  [NTOK*DIM];
__device__ float g_ctx[NTOK*DIM];
__device__ float g_a  [NTOK*DIM];
__device__ float g_x1 [NTOK*DIM];
__device__ float g_pos[SEQ*DIM];
__device__ float g_raw[NTOK*NEXP];
__device__ int   g_assign[NEXP*EROWS];
__device__ int   g_sE1[NTOK]; __device__ int g_sP1[NTOK]; __device__ float g_sG1[NTOK];
__device__ int   g_sE2[NTOK]; __device__ int g_sP2[NTOK]; __device__ float g_sG2[NTOK];
__device__ float g_ei [NEXP*EROWS*DIM];
__device__ float g_hid[NEXP*EROWS*HID];
__device__ float g_eo [NEXP*EROWS*DIM];
__device__ float g_loss[1];

// ---------------------------------------------------------------------------
// Helpers
// ---------------------------------------------------------------------------
__device__ __forceinline__ float tf32r(float x) {
    unsigned u;
    asm("cvt.rna.tf32.f32 %0, %1;" : "=r"(u) : "f"(x));
    return __uint_as_float(u);
}

__device__ __forceinline__ float blockReduceSum(float v) {
    __shared__ float sh[8];
    __shared__ float tot;
    int lane = threadIdx.x & 31, wid = threadIdx.x >> 5;
    #pragma unroll
    for (int o = 16; o; o >>= 1) v += __shfl_down_sync(0xFFFFFFFFu, v, o);
    if (lane == 0) sh[wid] = v;
    __syncthreads();
    if (wid == 0) {
        v = (lane < 8) ? sh[lane] : 0.f;
        #pragma unroll
        for (int o = 4; o; o >>= 1) v += __shfl_down_sync(0xFFFFFFFFu, v, o);
        if (lane == 0) tot = v;
    }
    __syncthreads();
    return tot;
}

// ---------------------------------------------------------------------------
// Threefry2x32, PARTITIONABLE path (verified PASS in R5).
// ---------------------------------------------------------------------------
#define TF_ROT(x0, x1, r)  { x0 += x1; x1 = ((x1 << (r)) | (x1 >> (32 - (r)))); x1 ^= x0; }
__device__ float jax_uniform_token(int j) {
    const unsigned KS0 = 0u;
    const unsigned KS1 = 1234u;
    const unsigned KS2 = 0x1BD11F08u;
    unsigned x0 = 0u;
    unsigned x1 = (unsigned)j;
    x0 += KS0; x1 += KS1;
    TF_ROT(x0, x1, 13) TF_ROT(x0, x1, 15) TF_ROT(x0, x1, 26) TF_ROT(x0, x1, 6)
    x0 += KS1; x1 += KS2 + 1u;
    TF_ROT(x0, x1, 17) TF_ROT(x0, x1, 29) TF_ROT(x0, x1, 16) TF_ROT(x0, x1, 24)
    x0 += KS2; x1 += KS0 + 2u;
    TF_ROT(x0, x1, 13) TF_ROT(x0, x1, 15) TF_ROT(x0, x1, 26) TF_ROT(x0, x1, 6)
    x0 += KS0; x1 += KS1 + 3u;
    TF_ROT(x0, x1, 17) TF_ROT(x0, x1, 29) TF_ROT(x0, x1, 16) TF_ROT(x0, x1, 24)
    x0 += KS1; x1 += KS2 + 4u;
    TF_ROT(x0, x1, 13) TF_ROT(x0, x1, 15) TF_ROT(x0, x1, 26) TF_ROT(x0, x1, 6)
    x0 += KS2; x1 += KS0 + 5u;
    unsigned bits = x0 ^ x1;
    unsigned f = (bits >> 9) | 0x3f800000u;
    return __uint_as_float(f) - 1.0f;
}

// ---------------------------------------------------------------------------
// fp32 SGEMM (routing-critical path: QKV/pos/Wo) — unchanged from R5.
// ---------------------------------------------------------------------------
template<bool BIAS, bool RELU>
__global__ __launch_bounds__(256, 2)
void sgemm_kernel(const float* __restrict__ A, const float* __restrict__ B,
                  const float* __restrict__ bias, float* __restrict__ C,
                  int M, int N, int K) {
    __shared__ float As[8][128];
    __shared__ float Bs[8][128];
    const int tid = threadIdx.x;
    const int tx = tid & 15, ty = tid >> 4;
    const int row0 = blockIdx.y * 128, col0 = blockIdx.x * 128;
    const int a_r = tid >> 1, a_c = (tid & 1) * 4;
    const int b_r = tid >> 5, b_c = (tid & 31) * 4;
    float acc[8][8];
    #pragma unroll
    for (int i = 0; i < 8; i++)
        #pragma unroll
        for (int j = 0; j < 8; j++) acc[i][j] = 0.f;
    const bool aok = (row0 + a_r) < M;
    const float* Aptr = A + (size_t)(row0 + a_r) * K + a_c;
    const float* Bptr = B + (size_t)b_r * N + col0 + b_c;
    for (int k0 = 0; k0 < K; k0 += 8) {
        float4 av = aok ? *(const float4*)(Aptr + k0) : make_float4(0.f, 0.f, 0.f, 0.f);
        As[a_c + 0][a_r] = av.x; As[a_c + 1][a_r] = av.y;
        As[a_c + 2][a_r] = av.z; As[a_c + 3][a_r] = av.w;
        *(float4*)&Bs[b_r][b_c] = *(const float4*)(Bptr + (size_t)k0 * N);
        __syncthreads();
        #pragma unroll
        for (int kk = 0; kk < 8; kk++) {
            float ar[8], br[8];
            *(float4*)&ar[0] = *(const float4*)&As[kk][ty * 4];
            *(float4*)&ar[4] = *(const float4*)&As[kk][64 + ty * 4];
            *(float4*)&br[0] = *(const float4*)&Bs[kk][tx * 4];
            *(float4*)&br[4] = *(const float4*)&Bs[kk][64 + tx * 4];
            #pragma unroll
            for (int i = 0; i < 8; i++)
                #pragma unroll
                for (int j = 0; j < 8; j++) acc[i][j] += ar[i] * br[j];
        }
        __syncthreads();
    }
    #pragma unroll
    for (int ig = 0; ig < 2; ig++) {
        #pragma unroll
        for (int ii = 0; ii < 4; ii++) {
            int r = row0 + ig * 64 + ty * 4 + ii;
            if (r >= M) continue;
            #pragma unroll
            for (int jg = 0; jg < 2; jg++) {
                int c = col0 + jg * 64 + tx * 4;
                float4 o;
                o.x = acc[ig * 4 + ii][jg * 4 + 0];
                o.y = acc[ig * 4 + ii][jg * 4 + 1];
                o.z = acc[ig * 4 + ii][jg * 4 + 2];
                o.w = acc[ig * 4 + ii][jg * 4 + 3];
                if (BIAS) {
                    o.x += bias[c];     o.y += bias[c + 1];
                    o.z += bias[c + 2]; o.w += bias[c + 3];
                }
                if (RELU) {
                    o.x = fmaxf(o.x, 0.f); o.y = fmaxf(o.y, 0.f);
                    o.z = fmaxf(o.z, 0.f); o.w = fmaxf(o.w, 0.f);
                }
                *(float4*)&C[(size_t)r * N + c] = o;
            }
        }
    }
}

// ---------------------------------------------------------------------------
// TF32 tensor-core GEMM (expert FFNs only — not routing-critical).
// C[M,N] = A[M,K] @ B[K,N], optional ReLU. M%128==0, N%128==0, K%32==0.
// 128x128x32 tile, 8 warps, mma.sync.m16n8k8.tf32, double-buffered smem.
// Batched over experts via blockIdx.z with explicit strides.
// ---------------------------------------------------------------------------
#define TBM 128
#define TBK 32
#define LDA_S 36   // bank: (36r+c)%32 = (4r+c)%32 -> conflict-free fragment reads
#define LDB_S 132  // bank: (132k+n)%32 = (4k+n)%32 -> conflict-free
#define A_TILE_F (TBM * LDA_S)          // 4608 floats
#define B_TILE_F (TBK * LDB_S)          // 4224 floats
#define STAGE_F  (A_TILE_F + B_TILE_F)  // 8832 floats
#define TF32_SMEM_BYTES (STAGE_F * 2 * 4)  // 70656 bytes

template<bool RELU>
__global__ __launch_bounds__(256)
void tf32_gemm_kernel(const float* __restrict__ A0, const float* __restrict__ B0,
                      float* __restrict__ C0, int M, int N, int K,
                      long long sA, long long sB, long long sC) {
    extern __shared__ float sm[];
    const float* A = A0 + (long long)blockIdx.z * sA;
    const float* B = B0 + (long long)blockIdx.z * sB;
    float*       C = C0 + (long long)blockIdx.z * sC;

    const int tid  = threadIdx.x;
    const int warp = tid >> 5;
    const int lane = tid & 31;
    const int wm = (warp & 1) * 64;      // warp row offset in tile
    const int wn = (warp >> 1) * 32;     // warp col offset in tile
    const int bm = blockIdx.y * TBM;
    const int bn = blockIdx.x * TBM;

    // global-load addressing (per thread: 4 float4 for A, 4 float4 for B)
    const int a_r0 = tid >> 3;           // + 32*i
    const int a_c  = (tid & 7) * 4;
    const int b_r0 = tid >> 5;           // + 8*i
    const int b_c  = (tid & 31) * 4;

    const int r  = lane >> 2;            // fragment row group
    const int cq = lane & 3;             // fragment col group

    float acc[4][4][4];
    #pragma unroll
    for (int mt = 0; mt < 4; mt++)
        #pragma unroll
        for (int nt = 0; nt < 4; nt++)
            #pragma unroll
            for (int q = 0; q < 4; q++) acc[mt][nt][q] = 0.f;

    const int KT = K / TBK;

    // preload tile 0
    {
        #pragma unroll
        for (int i = 0; i < 4; i++) {
            int ar = a_r0 + 32 * i;
            float4 va = *(const float4*)(A + (size_t)(bm + ar) * K + a_c);
            float* d = sm + ar * LDA_S + a_c;
            d[0] = tf32r(va.x); d[1] = tf32r(va.y); d[2] = tf32r(va.z); d[3] = tf32r(va.w);
            int br = b_r0 + 8 * i;
            float4 vb = *(const float4*)(B + (size_t)br * N + bn + b_c);
            float* e = sm + A_TILE_F + br * LDB_S + b_c;
            e[0] = tf32r(vb.x); e[1] = tf32r(vb.y); e[2] = tf32r(vb.z); e[3] = tf32r(vb.w);
        }
    }
    __syncthreads();

    for (int kt = 0; kt < KT; kt++) {
        const int cur = kt & 1;
        float4 pa[4], pb[4];
        const bool more = (kt + 1) < KT;
        if (more) {
            int k0 = (kt + 1) * TBK;
            #pragma unroll
            for (int i = 0; i < 4; i++) {
                pa[i] = *(const float4*)(A + (size_t)(bm + a_r0 + 32 * i) * K + k0 + a_c);
                pb[i] = *(const float4*)(B + (size_t)(k0 + b_r0 + 8 * i) * N + bn + b_c);
            }
        }

        const float* As = sm + cur * STAGE_F;
        const float* Bs = As + A_TILE_F;
        #pragma unroll
        for (int ks = 0; ks < 4; ks++) {
            const int k0 = ks * 8;
            unsigned af[4][4], bf[4][2];
            #pragma unroll
            for (int mt = 0; mt < 4; mt++) {
                const float* ab = As + (wm + mt * 16 + r) * LDA_S + k0 + cq;
                af[mt][0] = __float_as_uint(ab[0]);
                af[mt][1] = __float_as_uint(ab[8 * LDA_S]);
                af[mt][2] = __float_as_uint(ab[4]);
                af[mt][3] = __float_as_uint(ab[8 * LDA_S + 4]);
            }
            #pragma unroll
            for (int nt = 0; nt < 4; nt++) {
                const float* bb = Bs + (k0 + cq) * LDB_S + wn + nt * 8 + r;
                bf[nt][0] = __float_as_uint(bb[0]);
                bf[nt][1] = __float_as_uint(bb[4 * LDB_S]);
            }
            #pragma unroll
            for (int mt = 0; mt < 4; mt++)
                #pragma unroll
                for (int nt = 0; nt < 4; nt++) {
                    asm volatile(
                        "mma.sync.aligned.m16n8k8.row.col.f32.tf32.tf32.f32 "
                        "{%0,%1,%2,%3}, {%4,%5,%6,%7}, {%8,%9}, {%0,%1,%2,%3};"
                        : "+f"(acc[mt][nt][0]), "+f"(acc[mt][nt][1]),
                          "+f"(acc[mt][nt][2]), "+f"(acc[mt][nt][3])
                        : "r"(af[mt][0]), "r"(af[mt][1]), "r"(af[mt][2]), "r"(af[mt][3]),
                          "r"(bf[nt][0]), "r"(bf[nt][1]));
                }
        }

        if (more) {
            float* nAs = sm + (cur ^ 1) * STAGE_F;
            float* nBs = nAs + A_TILE_F;
            #pragma unroll
            for (int i = 0; i < 4; i++) {
                float* d = nAs + (a_r0 + 32 * i) * LDA_S + a_c;
                d[0] = tf32r(pa[i].x); d[1] = tf32r(pa[i].y);
                d[2] = tf32r(pa[i].z); d[3] = tf32r(pa[i].w);
                float* e = nBs + (b_r0 + 8 * i) * LDB_S + b_c;
                e[0] = tf32r(pb[i].x); e[1] = tf32r(pb[i].y);
                e[2] = tf32r(pb[i].z); e[3] = tf32r(pb[i].w);
            }
        }
        __syncthreads();
    }

    // epilogue: c0/c1 adjacent cols -> float2 stores
    #pragma unroll
    for (int mt = 0; mt < 4; mt++) {
        #pragma unroll
        for (int nt = 0; nt < 4; nt++) {
            int row = bm + wm + mt * 16 + r;
            int col = bn + wn + nt * 8 + 2 * cq;
            float2 v0, v1;
            v0.x = acc[mt][nt][0]; v0.y = acc[mt][nt][1];
            v1.x = acc[mt][nt][2]; v1.y = acc[mt][nt][3];
            if (RELU) {
                v0.x = fmaxf(v0.x, 0.f); v0.y = fmaxf(v0.y, 0.f);
                v1.x = fmaxf(v1.x, 0.f); v1.y = fmaxf(v1.y, 0.f);
            }
            *(float2*)&C[(size_t)row * N + col] = v0;
            *(float2*)&C[(size_t)(row + 8) * N + col] = v1;
        }
    }
}

// ---------------------------------------------------------------------------
// Init scratch (assign = -1, loss = 0)
// ---------------------------------------------------------------------------
__global__ void init_kernel() {
    int i = blockIdx.x * blockDim.x + threadIdx.x;
    if (i < NEXP * EROWS) g_assign[i] = -1;
    if (i == 0) g_loss[0] = 0.f;
}

// ---------------------------------------------------------------------------
// Fused rel-pos attention: one block per (b,h). 256 threads, 48KB static smem.
// ---------------------------------------------------------------------------
__global__ __launch_bounds__(256)
void attn_kernel(const float* __restrict__ u_bias, const float* __restrict__ v_bias) {
    __shared__ float qs[SEQ * DHEAD];
    __shared__ float ks[SEQ * DHEAD];
    __shared__ float vs[SEQ * DHEAD];
    __shared__ float ps[SEQ * DHEAD];
    __shared__ float pr[SEQ * SEQ];
    const int b = blockIdx.x >> 5;
    const int h = blockIdx.x & 31;
    const int tid = threadIdx.x;

    #pragma unroll
    for (int t = 0; t < 8; t++) {
        int idx = tid + t * 256;
        int s = idx >> 5, d = idx & 31;
        size_t g = ((size_t)((b * SEQ + s) * NHEAD + h)) * DHEAD + d;
        qs[idx] = g_q[g]; ks[idx] = g_k[g]; vs[idx] = g_v[g];
        ps[idx] = g_pos[(size_t)(s * NHEAD + h) * DHEAD + d];
    }
    __syncthreads();

    const int i  = tid >> 2;
    const int j0 = (tid & 3) * 16;
    float qd[32];

    #pragma unroll
    for (int d = 0; d < 32; d++) qd[d] = qs[i * 32 + d] + __ldg(&v_bias[h * 32 + d]);
    #pragma unroll
    for (int jj = 0; jj < 16; jj++) {
        int j = j0 + jj;
        float a = 0.f;
        #pragma unroll
        for (int d = 0; d < 32; d++) a += qd[d] * ps[j * 32 + d];
        pr[i * 64 + j] = a;
    }
    __syncthreads();

    float sh[16];
    #pragma unroll
    for (int jj = 0; jj < 16; jj++) {
        int c = j0 + jj;
        int f = (i + 1) * 64 + c;
        int ii = f / 65;
        int jp = f - ii * 65;
        sh[jj] = (jp == 0) ? 0.f : pr[ii * 64 + (jp - 1)];
    }
    __syncthreads();
    #pragma unroll
    for (int jj = 0; jj < 16; jj++) pr[i * 64 + j0 + jj] = sh[jj];
    __syncthreads();

    #pragma unroll
    for (int d = 0; d < 32; d++) qd[d] = qs[i * 32 + d] + __ldg(&u_bias[h * 32 + d]);
    #pragma unroll
    for (int jj = 0; jj < 16; jj++) {
        int j = j0 + jj;
        float a = 0.f;
        #pragma unroll
        for (int d = 0; d < 32; d++) a += qd[d] * ks[j * 32 + d];
        pr[i * 64 + j] = (a + pr[i * 64 + j]) * 0.03125f;
    }
    float m = -1e30f;
    #pragma unroll
    for (int jj = 0; jj < 16; jj++) m = fmaxf(m, pr[i * 64 + j0 + jj]);
    m = fmaxf(m, __shfl_xor_sync(0xFFFFFFFFu, m, 1));
    m = fmaxf(m, __shfl_xor_sync(0xFFFFFFFFu, m, 2));
    float ex[16], ssum = 0.f;
    #pragma unroll
    for (int jj = 0; jj < 16; jj++) { ex[jj] = expf(pr[i * 64 + j0 + jj] - m); ssum += ex[jj]; }
    ssum += __shfl_xor_sync(0xFFFFFFFFu, ssum, 1);
    ssum += __shfl_xor_sync(0xFFFFFFFFu, ssum, 2);
    float inv = 1.0f / ssum;
    #pragma unroll
    for (int jj = 0; jj < 16; jj++) pr[i * 64 + j0 + jj] = ex[jj] * inv;
    __syncthreads();

    const int i2 = tid >> 2;
    const int d0 = (tid & 3) * 8;
    float o[8] = {0.f, 0.f, 0.f, 0.f, 0.f, 0.f, 0.f, 0.f};
    for (int j = 0; j < 64; j++) {
        float aw = pr[i2 * 64 + j];
        #pragma unroll
        for (int dd = 0; dd < 8; dd++) o[dd] += aw * vs[j * 32 + d0 + dd];
    }
    size_t gbase = ((size_t)((b * SEQ + i2) * NHEAD + h)) * DHEAD + d0;
    #pragma unroll
    for (int dd = 0; dd < 8; dd++) g_ctx[gbase + dd] = o[dd];
}

// ---------------------------------------------------------------------------
// LN1: x1 = LayerNorm(g_a + x)
// ---------------------------------------------------------------------------
__global__ __launch_bounds__(256)
void ln1_kernel(const float* __restrict__ x, const float* __restrict__ gma,
                const float* __restrict__ bta) {
    int row = blockIdx.x, tid = threadIdx.x;
    const float* pa = g_a + (size_t)row * DIM;
    const float* pr = x   + (size_t)row * DIM;
    float vals[4], s = 0.f;
    #pragma unroll
    for (int t = 0; t < 4; t++) {
        int c = tid + t * 256;
        float v = pa[c] + pr[c];
        vals[t] = v; s += v;
    }
    s = blockReduceSum(s);
    float mu = s * (1.f / DIM);
    float vsum = 0.f;
    #pragma unroll
    for (int t = 0; t < 4; t++) { float d = vals[t] - mu; vsum += d * d; }
    vsum = blockReduceSum(vsum);
    float rstd = rsqrtf(vsum * (1.f / DIM) + 1e-5f);
    #pragma unroll
    for (int t = 0; t < 4; t++) {
        int c = tid + t * 256;
        g_x1[(size_t)row * DIM + c] = (vals[t] - mu) * rstd * gma[c] + bta[c];
    }
}

// ---------------------------------------------------------------------------
// Gating: raw = softmax(x1 @ w_gating) per token (one warp per token)
// ---------------------------------------------------------------------------
__global__ __launch_bounds__(256)
void gating_kernel(const float* __restrict__ wg) {
    int warp = (blockIdx.x * blockDim.x + threadIdx.x) >> 5;
    int lane = threadIdx.x & 31;
    if (warp >= NTOK) return;
    const float* xr = g_x1 + (size_t)warp * DIM;
    float a0 = 0.f, a1 = 0.f, a2 = 0.f, a3 = 0.f;
    for (int d = lane; d < DIM; d += 32) {
        float xv = xr[d];
        float4 w = ((const float4*)wg)[d];
        a0 += xv * w.x; a1 += xv * w.y; a2 += xv * w.z; a3 += xv * w.w;
    }
    #pragma unroll
    for (int o = 16; o; o >>= 1) {
        a0 += __shfl_down_sync(0xFFFFFFFFu, a0, o);
        a1 += __shfl_down_sync(0xFFFFFFFFu, a1, o);
        a2 += __shfl_down_sync(0xFFFFFFFFu, a2, o);
        a3 += __shfl_down_sync(0xFFFFFFFFu, a3, o);
    }
    if (lane == 0) {
        float m = fmaxf(fmaxf(a0, a1), fmaxf(a2, a3));
        float e0 = expf(a0 - m), e1 = expf(a1 - m), e2 = expf(a2 - m), e3 = expf(a3 - m);
        float s = e0 + e1 + e2 + e3;
        g_raw[warp * 4 + 0] = e0 / s;
        g_raw[warp * 4 + 1] = e1 / s;
        g_raw[warp * 4 + 2] = e2 / s;
        g_raw[warp * 4 + 3] = e3 / s;
    }
}

// ---------------------------------------------------------------------------
// Routing: serial per batch (matches JAX cumsum/capacity semantics exactly)
// ---------------------------------------------------------------------------
__global__ void routing_kernel() {
    if (threadIdx.x != 0) return;
    int b = blockIdx.x;
    int cnt1[4] = {0, 0, 0, 0};
    float dens[4] = {0.f, 0.f, 0.f, 0.f};
    float proxy[4] = {0.f, 0.f, 0.f, 0.f};
    int e2a[64]; float g2a[64]; bool k2a[64];

    for (int n = 0; n < SEQ; n++) {
        int tok = b * SEQ + n;
        float rr[4];
        #pragma unroll
        for (int e = 0; e < 4; e++) { rr[e] = g_raw[tok * 4 + e]; proxy[e] += rr[e]; }
        int e1 = 0; float g1 = rr[0];
        #pragma unroll
        for (int e = 1; e < 4; e++) if (rr[e] > g1) { g1 = rr[e]; e1 = e; }
        int e2 = -1; float g2 = -1.f;
        #pragma unroll
        for (int e = 0; e < 4; e++) {
            if (e == e1) continue;
            if (rr[e] > g2) { g2 = rr[e]; e2 = e; }
        }
        dens[e1] += 1.f;
        float denom = g1 + g2 + 1e-9f;
        float g1n = g1 / denom, g2n = g2 / denom;
        int p1 = cnt1[e1]++;
        g_sE1[tok] = e1;
        if (p1 < CAP) {
            g_sP1[tok] = p1; g_sG1[tok] = g1n;
            g_assign[(e1 * BATCH + b) * CAP + p1] = tok;
        } else {
            g_sP1[tok] = -1; g_sG1[tok] = 0.f;
        }
        float u = jax_uniform_token(tok);
        k2a[n] = (u < g2n / 0.2f);
        e2a[n] = e2; g2a[n] = g2n;
    }
    int c1c[4];
    #pragma unroll
    for (int e = 0; e < 4; e++) c1c[e] = cnt1[e] < CAP ? cnt1[e] : CAP;
    int cnt2[4] = {0, 0, 0, 0};
    for (int n = 0; n < SEQ; n++) {
        int tok = b * SEQ + n;
        g_sE2[tok] = e2a[n];
        g_sP2[tok] = -1; g_sG2[tok] = 0.f;
        if (k2a[n]) {
            int e2 = e2a[n];
            int p2 = cnt2[e2] + c1c[e2];
            cnt2[e2]++;
            if (p2 < CAP) {
                g_sP2[tok] = p2; g_sG2[tok] = g2a[n];
                g_assign[(e2 * BATCH + b) * CAP + p2] = tok;
            }
        }
    }
    float part = 0.f;
    #pragma unroll
    for (int e = 0; e < 4; e++) part += (proxy[e] * (1.f / SEQ)) * (dens[e] * (1.f / SEQ));
    atomicAdd(&g_loss[0], part);
}

// ---------------------------------------------------------------------------
// Gather dispatched tokens into expert input rows (zero for empty slots)
// ---------------------------------------------------------------------------
__global__ __launch_bounds__(256)
void gather_kernel() {
    int row = blockIdx.x;
    int tok = g_assign[row];
    float4* dst = ((float4*)g_ei) + (size_t)row * 256;
    if (tok >= 0) {
        const float4* src = ((const float4*)g_x1) + (size_t)tok * 256;
        dst[threadIdx.x] = src[threadIdx.x];
    } else {
        dst[threadIdx.x] = make_float4(0.f, 0.f, 0.f, 0.f);
    }
}

// ---------------------------------------------------------------------------
// Combine expert outputs + residual + LN2 -> d_out ; write loss scalar
// ---------------------------------------------------------------------------
__global__ __launch_bounds__(256)
void combine_ln2_kernel(const float* __restrict__ gma, const float* __restrict__ bta,
                        float* __restrict__ out, int out_size) {
    int tok = blockIdx.x, tid = threadIdx.x;
    int b = tok >> 6;
    int p1 = g_sP1[tok], p2 = g_sP2[tok];
    float g1 = g_sG1[tok], g2 = g_sG2[tok];
    const float* r1 = (p1 >= 0) ? g_eo + ((size_t)g_sE1[tok] * EROWS + b * CAP + p1) * DIM : nullptr;
    const float* r2 = (p2 >= 0) ? g_eo + ((size_t)g_sE2[tok] * EROWS + b * CAP + p2) * DIM : nullptr;
    const float* xr = g_x1 + (size_t)tok * DIM;
    float vals[4], s = 0.f;
    #pragma unroll
    for (int t = 0; t < 4; t++) {
        int c = tid + t * 256;
        float y = 0.f;
        if (r1) y += g1 * r1[c];
        if (r2) y += g2 * r2[c];
        float v = y + xr[c];
        vals[t] = v; s += v;
    }
    s = blockReduceSum(s);
    float mu = s * (1.f / DIM);
    float vsum = 0.f;
    #pragma unroll
    for (int t = 0; t < 4; t++) { float d = vals[t] - mu; vsum += d * d; }
    vsum = blockReduceSum(vsum);
    float rstd = rsqrtf(vsum * (1.f / DIM) + 1e-5f);
    #pragma unroll
    for (int t = 0; t < 4; t++) {
        int c = tid + t * 256;
        out[(size_t)tok * DIM + c] = (vals[t] - mu) * rstd * gma[c] + bta[c];
    }
    if (tok == 0 && tid == 0 && out_size > NTOK * DIM) {
        out[(size_t)NTOK * DIM] = g_loss[0] * ((float)(NEXP * NEXP) * 0.01f / (float)(BATCH * NEXP));
    }
}

// ---------------------------------------------------------------------------
// Host side
// ---------------------------------------------------------------------------
static void launch_gemm(const float* A, const float* B, const float* bias, float* C,
                        int M, int N, int K, bool biasF, bool reluF) {
    dim3 grid(N / 128, (M + 127) / 128);
    if (biasF)      sgemm_kernel<true,  false><<<grid, 256>>>(A, B, bias, C, M, N, K);
    else if (reluF) sgemm_kernel<false, true ><<<grid, 256>>>(A, B, bias, C, M, N, K);
    else            sgemm_kernel<false, false><<<grid, 256>>>(A, B, bias, C, M, N, K);
}

extern "C" void kernel_launch(void* const* d_in, const int* in_sizes, int n_in,
                              void* d_out, int out_size) {
    const float* x       = (const float*)d_in[0];
    const float* pos_enc = (const float*)d_in[1];
    const float* Wq      = (const float*)d_in[2];
    const float* bq      = (const float*)d_in[3];
    const float* Wk      = (const float*)d_in[4];
    const float* bk      = (const float*)d_in[5];
    const float* Wv      = (const float*)d_in[6];
    const float* bv      = (const float*)d_in[7];
    const float* Wpos    = (const float*)d_in[8];
    const float* u_bias  = (const float*)d_in[9];
    const float* v_bias  = (const float*)d_in[10];
    const float* Wo      = (const float*)d_in[11];
    const float* bo      = (const float*)d_in[12];
    const float* ln1_g   = (const float*)d_in[13];
    const float* ln1_b   = (const float*)d_in[14];
    const float* ln2_g   = (const float*)d_in[15];
    const float* ln2_b   = (const float*)d_in[16];
    const float* wg      = (const float*)d_in[17];
    const float* w1      = (const float*)d_in[18];
    const float* w2      = (const float*)d_in[19];
    float* out = (float*)d_out;

    float *q, *k, *v, *ctx, *a, *pos, *ei, *hid, *eo;
    cudaGetSymbolAddress((void**)&q,   g_q);
    cudaGetSymbolAddress((void**)&k,   g_k);
    cudaGetSymbolAddress((void**)&v,   g_v);
    cudaGetSymbolAddress((void**)&ctx, g_ctx);
    cudaGetSymbolAddress((void**)&a,   g_a);
    cudaGetSymbolAddress((void**)&pos, g_pos);
    cudaGetSymbolAddress((void**)&ei,  g_ei);
    cudaGetSymbolAddress((void**)&hid, g_hid);
    cudaGetSymbolAddress((void**)&eo,  g_eo);

    static bool attr_done = false;
    if (!attr_done) {
        cudaFuncSetAttribute(tf32_gemm_kernel<true>,
                             cudaFuncAttributeMaxDynamicSharedMemorySize, TF32_SMEM_BYTES);
        cudaFuncSetAttribute(tf32_gemm_kernel<false>,
                             cudaFuncAttributeMaxDynamicSharedMemorySize, TF32_SMEM_BYTES);
        attr_done = true;
    }

    init_kernel<<<128, 256>>>();

    // Projections (routing-critical: exact fp32)
    launch_gemm(x, Wq, bq, q, NTOK, DIM, DIM, true, false);
    launch_gemm(x, Wk, bk, k, NTOK, DIM, DIM, true, false);
    launch_gemm(x, Wv, bv, v, NTOK, DIM, DIM, true, false);
    launch_gemm(pos_enc, Wpos, nullptr, pos, SEQ, DIM, DIM, false, false);

    // Fused rel-pos attention core
    attn_kernel<<<BATCH * NHEAD, 256>>>(u_bias, v_bias);

    // Output projection + residual LN (routing-critical: exact fp32)
    launch_gemm(ctx, Wo, bo, a, NTOK, DIM, DIM, true, false);
    ln1_kernel<<<NTOK, 256>>>(x, ln1_g, ln1_b);

    // MoE
    gating_kernel<<<(NTOK * 32 + 255) / 256, 256>>>(wg);
    routing_kernel<<<BATCH, 32>>>();
    gather_kernel<<<NEXP * EROWS, 256>>>();

    // Expert FFNs on TF32 tensor cores (NOT routing-critical)
    {
        dim3 g1d(HID / 128, EROWS / 128, NEXP);
        tf32_gemm_kernel<true><<<g1d, 256, TF32_SMEM_BYTES>>>(
            ei, w1, hid, EROWS, HID, DIM,
            (long long)EROWS * DIM, (long long)DIM * HID, (long long)EROWS * HID);
        dim3 g2d(DIM / 128, EROWS / 128, NEXP);
        tf32_gemm_kernel<false><<<g2d, 256, TF32_SMEM_BYTES>>>(
            hid, w2, eo, EROWS, DIM, HID,
            (long long)EROWS * HID, (long long)HID * DIM, (long long)EROWS * DIM);
    }

    // Combine + residual + LN2 + loss
    combine_ln2_kernel<<<NTOK, 256>>>(ln2_g, ln2_b, out, out_size);
}

// round 8
// speedup vs baseline: 2.5339x; 1.0345x over previous
#include <cuda_runtime.h>
#include <cstdint>

// ---------------------------------------------------------------------------
// Problem constants
// ---------------------------------------------------------------------------
#define BATCH 256
#define SEQ   64
#define DIM   1024
#define NHEAD 32
#define DHEAD 32
#define NEXP  4
#define HID   1536
#define CAP   32
#define NTOK  (BATCH*SEQ)            // 16384
#define EROWS (BATCH*CAP)            // 8192 rows per expert

// ---------------------------------------------------------------------------
// Scratch (device globals; no allocation allowed)
// ---------------------------------------------------------------------------
__device__ float g_q  [NTOK*DIM];
__device__ float g_k  [NTOK*DIM];
__device__ float g_v  [NTOK*DIM];
__device__ float g_ctx[NTOK*DIM];
__device__ float g_a  [NTOK*DIM];
__device__ float g_x1 [NTOK*DIM];
__device__ float g_pos[SEQ*DIM];
__device__ float g_raw[NTOK*NEXP];
__device__ int   g_assign[NEXP*EROWS];
__device__ int   g_sE1[NTOK]; __device__ int g_sP1[NTOK]; __device__ float g_sG1[NTOK];
__device__ int   g_sE2[NTOK]; __device__ int g_sP2[NTOK]; __device__ float g_sG2[NTOK];
__device__ float g_ei [NEXP*EROWS*DIM];
__device__ float g_hid[NEXP*EROWS*HID];
__device__ float g_eo [NEXP*EROWS*DIM];
__device__ float g_loss[1];

// ---------------------------------------------------------------------------
// Helpers
// ---------------------------------------------------------------------------
__device__ __forceinline__ float tf32r(float x) {
    unsigned u;
    asm("cvt.rna.tf32.f32 %0, %1;" : "=r"(u) : "f"(x));
    return __uint_as_float(u);
}

__device__ __forceinline__ float blockReduceSum(float v) {
    __shared__ float sh[8];
    __shared__ float tot;
    int lane = threadIdx.x & 31, wid = threadIdx.x >> 5;
    #pragma unroll
    for (int o = 16; o; o >>= 1) v += __shfl_down_sync(0xFFFFFFFFu, v, o);
    if (lane == 0) sh[wid] = v;
    __syncthreads();
    if (wid == 0) {
        v = (lane < 8) ? sh[lane] : 0.f;
        #pragma unroll
        for (int o = 4; o; o >>= 1) v += __shfl_down_sync(0xFFFFFFFFu, v, o);
        if (lane == 0) tot = v;
    }
    __syncthreads();
    return tot;
}

// ---------------------------------------------------------------------------
// Threefry2x32, PARTITIONABLE path (verified PASS in R5/R6).
// ---------------------------------------------------------------------------
#define TF_ROT(x0, x1, r)  { x0 += x1; x1 = ((x1 << (r)) | (x1 >> (32 - (r)))); x1 ^= x0; }
__device__ float jax_uniform_token(int j) {
    const unsigned KS0 = 0u;
    const unsigned KS1 = 1234u;
    const unsigned KS2 = 0x1BD11F08u;
    unsigned x0 = 0u;
    unsigned x1 = (unsigned)j;
    x0 += KS0; x1 += KS1;
    TF_ROT(x0, x1, 13) TF_ROT(x0, x1, 15) TF_ROT(x0, x1, 26) TF_ROT(x0, x1, 6)
    x0 += KS1; x1 += KS2 + 1u;
    TF_ROT(x0, x1, 17) TF_ROT(x0, x1, 29) TF_ROT(x0, x1, 16) TF_ROT(x0, x1, 24)
    x0 += KS2; x1 += KS0 + 2u;
    TF_ROT(x0, x1, 13) TF_ROT(x0, x1, 15) TF_ROT(x0, x1, 26) TF_ROT(x0, x1, 6)
    x0 += KS0; x1 += KS1 + 3u;
    TF_ROT(x0, x1, 17) TF_ROT(x0, x1, 29) TF_ROT(x0, x1, 16) TF_ROT(x0, x1, 24)
    x0 += KS1; x1 += KS2 + 4u;
    TF_ROT(x0, x1, 13) TF_ROT(x0, x1, 15) TF_ROT(x0, x1, 26) TF_ROT(x0, x1, 6)
    x0 += KS2; x1 += KS0 + 5u;
    unsigned bits = x0 ^ x1;
    unsigned f = (bits >> 9) | 0x3f800000u;
    return __uint_as_float(f) - 1.0f;
}

// ---------------------------------------------------------------------------
// fp32 SGEMM (routing-critical path: QKV/pos/Wo) — unchanged (proven).
// ---------------------------------------------------------------------------
template<bool BIAS, bool RELU>
__global__ __launch_bounds__(256, 2)
void sgemm_kernel(const float* __restrict__ A, const float* __restrict__ B,
                  const float* __restrict__ bias, float* __restrict__ C,
                  int M, int N, int K) {
    __shared__ float As[8][128];
    __shared__ float Bs[8][128];
    const int tid = threadIdx.x;
    const int tx = tid & 15, ty = tid >> 4;
    const int row0 = blockIdx.y * 128, col0 = blockIdx.x * 128;
    const int a_r = tid >> 1, a_c = (tid & 1) * 4;
    const int b_r = tid >> 5, b_c = (tid & 31) * 4;
    float acc[8][8];
    #pragma unroll
    for (int i = 0; i < 8; i++)
        #pragma unroll
        for (int j = 0; j < 8; j++) acc[i][j] = 0.f;
    const bool aok = (row0 + a_r) < M;
    const float* Aptr = A + (size_t)(row0 + a_r) * K + a_c;
    const float* Bptr = B + (size_t)b_r * N + col0 + b_c;
    for (int k0 = 0; k0 < K; k0 += 8) {
        float4 av = aok ? *(const float4*)(Aptr + k0) : make_float4(0.f, 0.f, 0.f, 0.f);
        As[a_c + 0][a_r] = av.x; As[a_c + 1][a_r] = av.y;
        As[a_c + 2][a_r] = av.z; As[a_c + 3][a_r] = av.w;
        *(float4*)&Bs[b_r][b_c] = *(const float4*)(Bptr + (size_t)k0 * N);
        __syncthreads();
        #pragma unroll
        for (int kk = 0; kk < 8; kk++) {
            float ar[8], br[8];
            *(float4*)&ar[0] = *(const float4*)&As[kk][ty * 4];
            *(float4*)&ar[4] = *(const float4*)&As[kk][64 + ty * 4];
            *(float4*)&br[0] = *(const float4*)&Bs[kk][tx * 4];
            *(float4*)&br[4] = *(const float4*)&Bs[kk][64 + tx * 4];
            #pragma unroll
            for (int i = 0; i < 8; i++)
                #pragma unroll
                for (int j = 0; j < 8; j++) acc[i][j] += ar[i] * br[j];
        }
        __syncthreads();
    }
    #pragma unroll
    for (int ig = 0; ig < 2; ig++) {
        #pragma unroll
        for (int ii = 0; ii < 4; ii++) {
            int r = row0 + ig * 64 + ty * 4 + ii;
            if (r >= M) continue;
            #pragma unroll
            for (int jg = 0; jg < 2; jg++) {
                int c = col0 + jg * 64 + tx * 4;
                float4 o;
                o.x = acc[ig * 4 + ii][jg * 4 + 0];
                o.y = acc[ig * 4 + ii][jg * 4 + 1];
                o.z = acc[ig * 4 + ii][jg * 4 + 2];
                o.w = acc[ig * 4 + ii][jg * 4 + 3];
                if (BIAS) {
                    o.x += bias[c];     o.y += bias[c + 1];
                    o.z += bias[c + 2]; o.w += bias[c + 3];
                }
                if (RELU) {
                    o.x = fmaxf(o.x, 0.f); o.y = fmaxf(o.y, 0.f);
                    o.z = fmaxf(o.z, 0.f); o.w = fmaxf(o.w, 0.f);
                }
                *(float4*)&C[(size_t)r * N + c] = o;
            }
        }
    }
}

// ---------------------------------------------------------------------------
// TF32 tensor-core GEMM v2 (expert FFNs; not routing-critical).
// Block tile 128(M) x 256(N) x 32(K); 8 warps, warp tile 64x64 (mt=4, nt=8).
// A smem: k-interleaved layout (perm) so each A-fragment pair is one LDS.64;
//   row stride 40 words -> conflict-free ( (8r+2cq) mod 32 distinct/phase ).
// B smem: k-major, stride 264 words -> (8cq+r) mod 32 all-distinct, LDS.32.
// Double-buffered; global prefetch in registers.
//   perm(k) = (k & ~7) + 2*(k&3) + ((k>>2)&1)
// ---------------------------------------------------------------------------
#define WA_STRIDE 40
#define WB_STRIDE 264
#define WA_TILE  (128 * WA_STRIDE)       // 5120 words
#define WB_TILE  (32 * WB_STRIDE)        // 8448 words
#define WSTAGE   (WA_TILE + WB_TILE)     // 13568 words
#define WSMEM_BYTES (WSTAGE * 2 * 4)     // 108544 bytes

template<bool RELU>
__global__ __launch_bounds__(256, 1)
void tf32_gemm_wide(const float* __restrict__ A0, const float* __restrict__ B0,
                    float* __restrict__ C0, int M, int N, int K,
                    long long sA, long long sB, long long sC) {
    extern __shared__ float sm[];
    const float* A = A0 + (long long)blockIdx.z * sA;
    const float* B = B0 + (long long)blockIdx.z * sB;
    float*       C = C0 + (long long)blockIdx.z * sC;

    const int tid  = threadIdx.x;
    const int warp = tid >> 5;
    const int lane = tid & 31;
    const int wm = (warp & 1) * 64;
    const int wn = (warp >> 1) * 64;     // 0,64,128,192
    const int bm = blockIdx.y * 128;
    const int bn = blockIdx.x * 256;

    // A global-load addressing: 4 x float4 per thread
    const int a_r0 = tid >> 3;           // 0..31 (+32*i)
    const int a_c  = (tid & 7) * 4;      // 0,4,...,28
    // perm base for a 4-run starting at a_c: values land at pbase + 2j
    const int pbase = (a_c & 4) ? (a_c - 3) : a_c;

    const int r  = lane >> 2;            // 0..7
    const int cq = lane & 3;             // 0..3

    float acc[4][8][4];
    #pragma unroll
    for (int mt = 0; mt < 4; mt++)
        #pragma unroll
        for (int nt = 0; nt < 8; nt++)
            #pragma unroll
            for (int q = 0; q < 4; q++) acc[mt][nt][q] = 0.f;

    const int KT = K / 32;

    // ---- preload tile 0 ----
    {
        float* As = sm;
        float* Bs = sm + WA_TILE;
        #pragma unroll
        for (int i = 0; i < 4; i++) {
            int ar = a_r0 + 32 * i;
            float4 v = *(const float4*)(A + (size_t)(bm + ar) * K + a_c);
            float* d = As + ar * WA_STRIDE + pbase;
            d[0] = tf32r(v.x); d[2] = tf32r(v.y); d[4] = tf32r(v.z); d[6] = tf32r(v.w);
        }
        #pragma unroll
        for (int j = 0; j < 8; j++) {
            int idx = tid + 256 * j;
            int brow = idx >> 6;                 // 0..31
            int bcol = (idx & 63) * 4;           // 0..252
            float4 v = *(const float4*)(B + (size_t)brow * N + bn + bcol);
            float4 w;
            w.x = tf32r(v.x); w.y = tf32r(v.y); w.z = tf32r(v.z); w.w = tf32r(v.w);
            *(float4*)(Bs + brow * WB_STRIDE + bcol) = w;
        }
    }
    __syncthreads();

    for (int kt = 0; kt < KT; kt++) {
        const int cur = kt & 1;
        const float* As = sm + cur * WSTAGE;
        const float* Bs = As + WA_TILE;
        const bool more = (kt + 1) < KT;

        float4 pa[4], pb[8];
        if (more) {
            const int k0g = (kt + 1) * 32;
            #pragma unroll
            for (int i = 0; i < 4; i++)
                pa[i] = *(const float4*)(A + (size_t)(bm + a_r0 + 32 * i) * K + k0g + a_c);
            #pragma unroll
            for (int j = 0; j < 8; j++) {
                int idx = tid + 256 * j;
                int brow = idx >> 6;
                int bcol = (idx & 63) * 4;
                pb[j] = *(const float4*)(B + (size_t)(k0g + brow) * N + bn + bcol);
            }
        }

        #pragma unroll
        for (int ks = 0; ks < 4; ks++) {
            const int k0 = ks * 8;
            unsigned af[4][4];
            #pragma unroll
            for (int mt = 0; mt < 4; mt++) {
                const float* ab = As + (wm + mt * 16 + r) * WA_STRIDE + k0 + 2 * cq;
                float2 lo = *(const float2*)ab;                    // (r,cq),(r,cq+4)
                float2 hi = *(const float2*)(ab + 8 * WA_STRIDE);  // (r+8,...)
                af[mt][0] = __float_as_uint(lo.x);
                af[mt][1] = __float_as_uint(hi.x);
                af[mt][2] = __float_as_uint(lo.y);
                af[mt][3] = __float_as_uint(hi.y);
            }
            unsigned bf[8][2];
            #pragma unroll
            for (int nt = 0; nt < 8; nt++) {
                const float* bb = Bs + (k0 + cq) * WB_STRIDE + wn + nt * 8 + r;
                bf[nt][0] = __float_as_uint(bb[0]);
                bf[nt][1] = __float_as_uint(bb[4 * WB_STRIDE]);
            }
            #pragma unroll
            for (int mt = 0; mt < 4; mt++)
                #pragma unroll
                for (int nt = 0; nt < 8; nt++) {
                    asm volatile(
                        "mma.sync.aligned.m16n8k8.row.col.f32.tf32.tf32.f32 "
                        "{%0,%1,%2,%3}, {%4,%5,%6,%7}, {%8,%9}, {%0,%1,%2,%3};"
                        : "+f"(acc[mt][nt][0]), "+f"(acc[mt][nt][1]),
                          "+f"(acc[mt][nt][2]), "+f"(acc[mt][nt][3])
                        : "r"(af[mt][0]), "r"(af[mt][1]), "r"(af[mt][2]), "r"(af[mt][3]),
                          "r"(bf[nt][0]), "r"(bf[nt][1]));
                }
        }

        if (more) {
            float* nAs = sm + (cur ^ 1) * WSTAGE;
            float* nBs = nAs + WA_TILE;
            #pragma unroll
            for (int i = 0; i < 4; i++) {
                float* d = nAs + (a_r0 + 32 * i) * WA_STRIDE + pbase;
                d[0] = tf32r(pa[i].x); d[2] = tf32r(pa[i].y);
                d[4] = tf32r(pa[i].z); d[6] = tf32r(pa[i].w);
            }
            #pragma unroll
            for (int j = 0; j < 8; j++) {
                int idx = tid + 256 * j;
                int brow = idx >> 6;
                int bcol = (idx & 63) * 4;
                float4 w;
                w.x = tf32r(pb[j].x); w.y = tf32r(pb[j].y);
                w.z = tf32r(pb[j].z); w.w = tf32r(pb[j].w);
                *(float4*)(nBs + brow * WB_STRIDE + bcol) = w;
            }
        }
        __syncthreads();
    }

    // epilogue
    #pragma unroll
    for (int mt = 0; mt < 4; mt++) {
        #pragma unroll
        for (int nt = 0; nt < 8; nt++) {
            int row = bm + wm + mt * 16 + r;
            int col = bn + wn + nt * 8 + 2 * cq;
            float2 v0, v1;
            v0.x = acc[mt][nt][0]; v0.y = acc[mt][nt][1];
            v1.x = acc[mt][nt][2]; v1.y = acc[mt][nt][3];
            if (RELU) {
                v0.x = fmaxf(v0.x, 0.f); v0.y = fmaxf(v0.y, 0.f);
                v1.x = fmaxf(v1.x, 0.f); v1.y = fmaxf(v1.y, 0.f);
            }
            *(float2*)&C[(size_t)row * N + col] = v0;
            *(float2*)&C[(size_t)(row + 8) * N + col] = v1;
        }
    }
}

// ---------------------------------------------------------------------------
// Init scratch (assign = -1, loss = 0)
// ---------------------------------------------------------------------------
__global__ void init_kernel() {
    int i = blockIdx.x * blockDim.x + threadIdx.x;
    if (i < NEXP * EROWS) g_assign[i] = -1;
    if (i == 0) g_loss[0] = 0.f;
}

// ---------------------------------------------------------------------------
// Fused rel-pos attention: one block per (b,h). 256 threads, 48KB static smem.
// ---------------------------------------------------------------------------
__global__ __launch_bounds__(256)
void attn_kernel(const float* __restrict__ u_bias, const float* __restrict__ v_bias) {
    __shared__ float qs[SEQ * DHEAD];
    __shared__ float ks[SEQ * DHEAD];
    __shared__ float vs[SEQ * DHEAD];
    __shared__ float ps[SEQ * DHEAD];
    __shared__ float pr[SEQ * SEQ];
    const int b = blockIdx.x >> 5;
    const int h = blockIdx.x & 31;
    const int tid = threadIdx.x;

    #pragma unroll
    for (int t = 0; t < 8; t++) {
        int idx = tid + t * 256;
        int s = idx >> 5, d = idx & 31;
        size_t g = ((size_t)((b * SEQ + s) * NHEAD + h)) * DHEAD + d;
        qs[idx] = g_q[g]; ks[idx] = g_k[g]; vs[idx] = g_v[g];
        ps[idx] = g_pos[(size_t)(s * NHEAD + h) * DHEAD + d];
    }
    __syncthreads();

    const int i  = tid >> 2;
    const int j0 = (tid & 3) * 16;
    float qd[32];

    #pragma unroll
    for (int d = 0; d < 32; d++) qd[d] = qs[i * 32 + d] + __ldg(&v_bias[h * 32 + d]);
    #pragma unroll
    for (int jj = 0; jj < 16; jj++) {
        int j = j0 + jj;
        float a = 0.f;
        #pragma unroll
        for (int d = 0; d < 32; d++) a += qd[d] * ps[j * 32 + d];
        pr[i * 64 + j] = a;
    }
    __syncthreads();

    float sh[16];
    #pragma unroll
    for (int jj = 0; jj < 16; jj++) {
        int c = j0 + jj;
        int f = (i + 1) * 64 + c;
        int ii = f / 65;
        int jp = f - ii * 65;
        sh[jj] = (jp == 0) ? 0.f : pr[ii * 64 + (jp - 1)];
    }
    __syncthreads();
    #pragma unroll
    for (int jj = 0; jj < 16; jj++) pr[i * 64 + j0 + jj] = sh[jj];
    __syncthreads();

    #pragma unroll
    for (int d = 0; d < 32; d++) qd[d] = qs[i * 32 + d] + __ldg(&u_bias[h * 32 + d]);
    #pragma unroll
    for (int jj = 0; jj < 16; jj++) {
        int j = j0 + jj;
        float a = 0.f;
        #pragma unroll
        for (int d = 0; d < 32; d++) a += qd[d] * ks[j * 32 + d];
        pr[i * 64 + j] = (a + pr[i * 64 + j]) * 0.03125f;
    }
    float m = -1e30f;
    #pragma unroll
    for (int jj = 0; jj < 16; jj++) m = fmaxf(m, pr[i * 64 + j0 + jj]);
    m = fmaxf(m, __shfl_xor_sync(0xFFFFFFFFu, m, 1));
    m = fmaxf(m, __shfl_xor_sync(0xFFFFFFFFu, m, 2));
    float ex[16], ssum = 0.f;
    #pragma unroll
    for (int jj = 0; jj < 16; jj++) { ex[jj] = expf(pr[i * 64 + j0 + jj] - m); ssum += ex[jj]; }
    ssum += __shfl_xor_sync(0xFFFFFFFFu, ssum, 1);
    ssum += __shfl_xor_sync(0xFFFFFFFFu, ssum, 2);
    float inv = 1.0f / ssum;
    #pragma unroll
    for (int jj = 0; jj < 16; jj++) pr[i * 64 + j0 + jj] = ex[jj] * inv;
    __syncthreads();

    const int i2 = tid >> 2;
    const int d0 = (tid & 3) * 8;
    float o[8] = {0.f, 0.f, 0.f, 0.f, 0.f, 0.f, 0.f, 0.f};
    for (int j = 0; j < 64; j++) {
        float aw = pr[i2 * 64 + j];
        #pragma unroll
        for (int dd = 0; dd < 8; dd++) o[dd] += aw * vs[j * 32 + d0 + dd];
    }
    size_t gbase = ((size_t)((b * SEQ + i2) * NHEAD + h)) * DHEAD + d0;
    #pragma unroll
    for (int dd = 0; dd < 8; dd++) g_ctx[gbase + dd] = o[dd];
}

// ---------------------------------------------------------------------------
// LN1: x1 = LayerNorm(g_a + x)
// ---------------------------------------------------------------------------
__global__ __launch_bounds__(256)
void ln1_kernel(const float* __restrict__ x, const float* __restrict__ gma,
                const float* __restrict__ bta) {
    int row = blockIdx.x, tid = threadIdx.x;
    const float* pa = g_a + (size_t)row * DIM;
    const float* pr = x   + (size_t)row * DIM;
    float vals[4], s = 0.f;
    #pragma unroll
    for (int t = 0; t < 4; t++) {
        int c = tid + t * 256;
        float v = pa[c] + pr[c];
        vals[t] = v; s += v;
    }
    s = blockReduceSum(s);
    float mu = s * (1.f / DIM);
    float vsum = 0.f;
    #pragma unroll
    for (int t = 0; t < 4; t++) { float d = vals[t] - mu; vsum += d * d; }
    vsum = blockReduceSum(vsum);
    float rstd = rsqrtf(vsum * (1.f / DIM) + 1e-5f);
    #pragma unroll
    for (int t = 0; t < 4; t++) {
        int c = tid + t * 256;
        g_x1[(size_t)row * DIM + c] = (vals[t] - mu) * rstd * gma[c] + bta[c];
    }
}

// ---------------------------------------------------------------------------
// Gating: raw = softmax(x1 @ w_gating) per token (one warp per token)
// ---------------------------------------------------------------------------
__global__ __launch_bounds__(256)
void gating_kernel(const float* __restrict__ wg) {
    int warp = (blockIdx.x * blockDim.x + threadIdx.x) >> 5;
    int lane = threadIdx.x & 31;
    if (warp >= NTOK) return;
    const float* xr = g_x1 + (size_t)warp * DIM;
    float a0 = 0.f, a1 = 0.f, a2 = 0.f, a3 = 0.f;
    for (int d = lane; d < DIM; d += 32) {
        float xv = xr[d];
        float4 w = ((const float4*)wg)[d];
        a0 += xv * w.x; a1 += xv * w.y; a2 += xv * w.z; a3 += xv * w.w;
    }
    #pragma unroll
    for (int o = 16; o; o >>= 1) {
        a0 += __shfl_down_sync(0xFFFFFFFFu, a0, o);
        a1 += __shfl_down_sync(0xFFFFFFFFu, a1, o);
        a2 += __shfl_down_sync(0xFFFFFFFFu, a2, o);
        a3 += __shfl_down_sync(0xFFFFFFFFu, a3, o);
    }
    if (lane == 0) {
        float m = fmaxf(fmaxf(a0, a1), fmaxf(a2, a3));
        float e0 = expf(a0 - m), e1 = expf(a1 - m), e2 = expf(a2 - m), e3 = expf(a3 - m);
        float s = e0 + e1 + e2 + e3;
        g_raw[warp * 4 + 0] = e0 / s;
        g_raw[warp * 4 + 1] = e1 / s;
        g_raw[warp * 4 + 2] = e2 / s;
        g_raw[warp * 4 + 3] = e3 / s;
    }
}

// ---------------------------------------------------------------------------
// Routing: serial per batch (matches JAX cumsum/capacity semantics exactly)
// ---------------------------------------------------------------------------
__global__ void routing_kernel() {
    if (threadIdx.x != 0) return;
    int b = blockIdx.x;
    int cnt1[4] = {0, 0, 0, 0};
    float dens[4] = {0.f, 0.f, 0.f, 0.f};
    float proxy[4] = {0.f, 0.f, 0.f, 0.f};
    int e2a[64]; float g2a[64]; bool k2a[64];

    for (int n = 0; n < SEQ; n++) {
        int tok = b * SEQ + n;
        float rr[4];
        #pragma unroll
        for (int e = 0; e < 4; e++) { rr[e] = g_raw[tok * 4 + e]; proxy[e] += rr[e]; }
        int e1 = 0; float g1 = rr[0];
        #pragma unroll
        for (int e = 1; e < 4; e++) if (rr[e] > g1) { g1 = rr[e]; e1 = e; }
        int e2 = -1; float g2 = -1.f;
        #pragma unroll
        for (int e = 0; e < 4; e++) {
            if (e == e1) continue;
            if (rr[e] > g2) { g2 = rr[e]; e2 = e; }
        }
        dens[e1] += 1.f;
        float denom = g1 + g2 + 1e-9f;
        float g1n = g1 / denom, g2n = g2 / denom;
        int p1 = cnt1[e1]++;
        g_sE1[tok] = e1;
        if (p1 < CAP) {
            g_sP1[tok] = p1; g_sG1[tok] = g1n;
            g_assign[(e1 * BATCH + b) * CAP + p1] = tok;
        } else {
            g_sP1[tok] = -1; g_sG1[tok] = 0.f;
        }
        float u = jax_uniform_token(tok);
        k2a[n] = (u < g2n / 0.2f);
        e2a[n] = e2; g2a[n] = g2n;
    }
    int c1c[4];
    #pragma unroll
    for (int e = 0; e < 4; e++) c1c[e] = cnt1[e] < CAP ? cnt1[e] : CAP;
    int cnt2[4] = {0, 0, 0, 0};
    for (int n = 0; n < SEQ; n++) {
        int tok = b * SEQ + n;
        g_sE2[tok] = e2a[n];
        g_sP2[tok] = -1; g_sG2[tok] = 0.f;
        if (k2a[n]) {
            int e2 = e2a[n];
            int p2 = cnt2[e2] + c1c[e2];
            cnt2[e2]++;
            if (p2 < CAP) {
                g_sP2[tok] = p2; g_sG2[tok] = g2a[n];
                g_assign[(e2 * BATCH + b) * CAP + p2] = tok;
            }
        }
    }
    float part = 0.f;
    #pragma unroll
    for (int e = 0; e < 4; e++) part += (proxy[e] * (1.f / SEQ)) * (dens[e] * (1.f / SEQ));
    atomicAdd(&g_loss[0], part);
}

// ---------------------------------------------------------------------------
// Gather dispatched tokens into expert input rows (zero for empty slots)
// ---------------------------------------------------------------------------
__global__ __launch_bounds__(256)
void gather_kernel() {
    int row = blockIdx.x;
    int tok = g_assign[row];
    float4* dst = ((float4*)g_ei) + (size_t)row * 256;
    if (tok >= 0) {
        const float4* src = ((const float4*)g_x1) + (size_t)tok * 256;
        dst[threadIdx.x] = src[threadIdx.x];
    } else {
        dst[threadIdx.x] = make_float4(0.f, 0.f, 0.f, 0.f);
    }
}

// ---------------------------------------------------------------------------
// Combine expert outputs + residual + LN2 -> d_out ; write loss scalar
// ---------------------------------------------------------------------------
__global__ __launch_bounds__(256)
void combine_ln2_kernel(const float* __restrict__ gma, const float* __restrict__ bta,
                        float* __restrict__ out, int out_size) {
    int tok = blockIdx.x, tid = threadIdx.x;
    int b = tok >> 6;
    int p1 = g_sP1[tok], p2 = g_sP2[tok];
    float g1 = g_sG1[tok], g2 = g_sG2[tok];
    const float* r1 = (p1 >= 0) ? g_eo + ((size_t)g_sE1[tok] * EROWS + b * CAP + p1) * DIM : nullptr;
    const float* r2 = (p2 >= 0) ? g_eo + ((size_t)g_sE2[tok] * EROWS + b * CAP + p2) * DIM : nullptr;
    const float* xr = g_x1 + (size_t)tok * DIM;
    float vals[4], s = 0.f;
    #pragma unroll
    for (int t = 0; t < 4; t++) {
        int c = tid + t * 256;
        float y = 0.f;
        if (r1) y += g1 * r1[c];
        if (r2) y += g2 * r2[c];
        float v = y + xr[c];
        vals[t] = v; s += v;
    }
    s = blockReduceSum(s);
    float mu = s * (1.f / DIM);
    float vsum = 0.f;
    #pragma unroll
    for (int t = 0; t < 4; t++) { float d = vals[t] - mu; vsum += d * d; }
    vsum = blockReduceSum(vsum);
    float rstd = rsqrtf(vsum * (1.f / DIM) + 1e-5f);
    #pragma unroll
    for (int t = 0; t < 4; t++) {
        int c = tid + t * 256;
        out[(size_t)tok * DIM + c] = (vals[t] - mu) * rstd * gma[c] + bta[c];
    }
    if (tok == 0 && tid == 0 && out_size > NTOK * DIM) {
        out[(size_t)NTOK * DIM] = g_loss[0] * ((float)(NEXP * NEXP) * 0.01f / (float)(BATCH * NEXP));
    }
}

// ---------------------------------------------------------------------------
// Host side
// ---------------------------------------------------------------------------
static void launch_gemm(const float* A, const float* B, const float* bias, float* C,
                        int M, int N, int K, bool biasF, bool reluF) {
    dim3 grid(N / 128, (M + 127) / 128);
    if (biasF)      sgemm_kernel<true,  false><<<grid, 256>>>(A, B, bias, C, M, N, K);
    else if (reluF) sgemm_kernel<false, true ><<<grid, 256>>>(A, B, bias, C, M, N, K);
    else            sgemm_kernel<false, false><<<grid, 256>>>(A, B, bias, C, M, N, K);
}

extern "C" void kernel_launch(void* const* d_in, const int* in_sizes, int n_in,
                              void* d_out, int out_size) {
    const float* x       = (const float*)d_in[0];
    const float* pos_enc = (const float*)d_in[1];
    const float* Wq      = (const float*)d_in[2];
    const float* bq      = (const float*)d_in[3];
    const float* Wk      = (const float*)d_in[4];
    const float* bk      = (const float*)d_in[5];
    const float* Wv      = (const float*)d_in[6];
    const float* bv      = (const float*)d_in[7];
    const float* Wpos    = (const float*)d_in[8];
    const float* u_bias  = (const float*)d_in[9];
    const float* v_bias  = (const float*)d_in[10];
    const float* Wo      = (const float*)d_in[11];
    const float* bo      = (const float*)d_in[12];
    const float* ln1_g   = (const float*)d_in[13];
    const float* ln1_b   = (const float*)d_in[14];
    const float* ln2_g   = (const float*)d_in[15];
    const float* ln2_b   = (const float*)d_in[16];
    const float* wg      = (const float*)d_in[17];
    const float* w1      = (const float*)d_in[18];
    const float* w2      = (const float*)d_in[19];
    float* out = (float*)d_out;

    float *q, *k, *v, *ctx, *a, *pos, *ei, *hid, *eo;
    cudaGetSymbolAddress((void**)&q,   g_q);
    cudaGetSymbolAddress((void**)&k,   g_k);
    cudaGetSymbolAddress((void**)&v,   g_v);
    cudaGetSymbolAddress((void**)&ctx, g_ctx);
    cudaGetSymbolAddress((void**)&a,   g_a);
    cudaGetSymbolAddress((void**)&pos, g_pos);
    cudaGetSymbolAddress((void**)&ei,  g_ei);
    cudaGetSymbolAddress((void**)&hid, g_hid);
    cudaGetSymbolAddress((void**)&eo,  g_eo);

    static bool attr_done = false;
    if (!attr_done) {
        cudaFuncSetAttribute(tf32_gemm_wide<true>,
                             cudaFuncAttributeMaxDynamicSharedMemorySize, WSMEM_BYTES);
        cudaFuncSetAttribute(tf32_gemm_wide<false>,
                             cudaFuncAttributeMaxDynamicSharedMemorySize, WSMEM_BYTES);
        attr_done = true;
    }

    init_kernel<<<128, 256>>>();

    // Projections (routing-critical: exact fp32)
    launch_gemm(x, Wq, bq, q, NTOK, DIM, DIM, true, false);
    launch_gemm(x, Wk, bk, k, NTOK, DIM, DIM, true, false);
    launch_gemm(x, Wv, bv, v, NTOK, DIM, DIM, true, false);
    launch_gemm(pos_enc, Wpos, nullptr, pos, SEQ, DIM, DIM, false, false);

    // Fused rel-pos attention core
    attn_kernel<<<BATCH * NHEAD, 256>>>(u_bias, v_bias);

    // Output projection + residual LN (routing-critical: exact fp32)
    launch_gemm(ctx, Wo, bo, a, NTOK, DIM, DIM, true, false);
    ln1_kernel<<<NTOK, 256>>>(x, ln1_g, ln1_b);

    // MoE
    gating_kernel<<<(NTOK * 32 + 255) / 256, 256>>>(wg);
    routing_kernel<<<BATCH, 32>>>();
    gather_kernel<<<NEXP * EROWS, 256>>>();

    // Expert FFNs on TF32 tensor cores (NOT routing-critical)
    {
        dim3 g1d(HID / 256, EROWS / 128, NEXP);   // (6, 64, 4)
        tf32_gemm_wide<true><<<g1d, 256, WSMEM_BYTES>>>(
            ei, w1, hid, EROWS, HID, DIM,
            (long long)EROWS * DIM, (long long)DIM * HID, (long long)EROWS * HID);
        dim3 g2d(DIM / 256, EROWS / 128, NEXP);   // (4, 64, 4)
        tf32_gemm_wide<false><<<g2d, 256, WSMEM_BYTES>>>(
            hid, w2, eo, EROWS, DIM, HID,
            (long long)EROWS * HID, (long long)HID * DIM, (long long)EROWS * DIM);
    }

    // Combine + residual + LN2 + loss
    combine_ln2_kernel<<<NTOK, 256>>>(ln2_g, ln2_b, out, out_size);
}

// round 13
// speedup vs baseline: 2.5818x; 1.0189x over previous
#include <cuda_runtime.h>
#include <cstdint>

// ---------------------------------------------------------------------------
// Problem constants
// ---------------------------------------------------------------------------
#define BATCH 256
#define SEQ   64
#define DIM   1024
#define NHEAD 32
#define DHEAD 32
#define NEXP  4
#define HID   1536
#define CAP   32
#define NTOK  (BATCH*SEQ)            // 16384
#define EROWS (BATCH*CAP)            // 8192 rows per expert

// ---------------------------------------------------------------------------
// Scratch (device globals; no allocation allowed)
// ---------------------------------------------------------------------------
__device__ float g_q  [NTOK*DIM];
__device__ float g_k  [NTOK*DIM];
__device__ float g_v  [NTOK*DIM];
__device__ float g_ctx[NTOK*DIM];
__device__ float g_a  [NTOK*DIM];
__device__ float g_x1 [NTOK*DIM];
__device__ float g_pos[SEQ*DIM];
__device__ float g_raw[NTOK*NEXP];
__device__ int   g_assign[NEXP*EROWS];
__device__ int   g_sE1[NTOK]; __device__ int g_sP1[NTOK]; __device__ float g_sG1[NTOK];
__device__ int   g_sE2[NTOK]; __device__ int g_sP2[NTOK]; __device__ float g_sG2[NTOK];
__device__ float g_ei [NEXP*EROWS*DIM];
__device__ float g_hid[NEXP*EROWS*HID];
__device__ float g_eo [NEXP*EROWS*DIM];
__device__ float g_loss[1];

// ---------------------------------------------------------------------------
// Helpers
// ---------------------------------------------------------------------------
__device__ __forceinline__ float tf32r(float x) {
    unsigned u;
    asm("cvt.rna.tf32.f32 %0, %1;" : "=r"(u) : "f"(x));
    return __uint_as_float(u);
}

__device__ __forceinline__ float blockReduceSum(float v) {
    __shared__ float sh[8];
    __shared__ float tot;
    int lane = threadIdx.x & 31, wid = threadIdx.x >> 5;
    #pragma unroll
    for (int o = 16; o; o >>= 1) v += __shfl_down_sync(0xFFFFFFFFu, v, o);
    if (lane == 0) sh[wid] = v;
    __syncthreads();
    if (wid == 0) {
        v = (lane < 8) ? sh[lane] : 0.f;
        #pragma unroll
        for (int o = 4; o; o >>= 1) v += __shfl_down_sync(0xFFFFFFFFu, v, o);
        if (lane == 0) tot = v;
    }
    __syncthreads();
    return tot;
}

// ---------------------------------------------------------------------------
// Threefry2x32, PARTITIONABLE path (verified PASS R5/R6/R8).
// ---------------------------------------------------------------------------
#define TF_ROT(x0, x1, r)  { x0 += x1; x1 = ((x1 << (r)) | (x1 >> (32 - (r)))); x1 ^= x0; }
__device__ float jax_uniform_token(int j) {
    const unsigned KS0 = 0u;
    const unsigned KS1 = 1234u;
    const unsigned KS2 = 0x1BD11F08u;
    unsigned x0 = 0u;
    unsigned x1 = (unsigned)j;
    x0 += KS0; x1 += KS1;
    TF_ROT(x0, x1, 13) TF_ROT(x0, x1, 15) TF_ROT(x0, x1, 26) TF_ROT(x0, x1, 6)
    x0 += KS1; x1 += KS2 + 1u;
    TF_ROT(x0, x1, 17) TF_ROT(x0, x1, 29) TF_ROT(x0, x1, 16) TF_ROT(x0, x1, 24)
    x0 += KS2; x1 += KS0 + 2u;
    TF_ROT(x0, x1, 13) TF_ROT(x0, x1, 15) TF_ROT(x0, x1, 26) TF_ROT(x0, x1, 6)
    x0 += KS0; x1 += KS1 + 3u;
    TF_ROT(x0, x1, 17) TF_ROT(x0, x1, 29) TF_ROT(x0, x1, 16) TF_ROT(x0, x1, 24)
    x0 += KS1; x1 += KS2 + 4u;
    TF_ROT(x0, x1, 13) TF_ROT(x0, x1, 15) TF_ROT(x0, x1, 26) TF_ROT(x0, x1, 6)
    x0 += KS2; x1 += KS0 + 5u;
    unsigned bits = x0 ^ x1;
    unsigned f = (bits >> 9) | 0x3f800000u;
    return __uint_as_float(f) - 1.0f;
}

// ---------------------------------------------------------------------------
// fp32 SGEMM v2 (routing-critical: QKV/pos/Wo).
// 128x128 tile, K-step 16, DOUBLE-BUFFERED smem + register prefetch.
// Per-element k-accumulation order identical to proven kernel.
// (R11 bug fixed: in-loop pb1 prefetch is same k-row, +4 columns.)
// ---------------------------------------------------------------------------
template<bool BIAS>
__global__ __launch_bounds__(256, 2)
void sgemm_kernel(const float* __restrict__ A, const float* __restrict__ B,
                  const float* __restrict__ bias, float* __restrict__ C,
                  int M, int N, int K) {
    __shared__ float As[2][16][128];
    __shared__ float Bs[2][16][128];
    const int tid = threadIdx.x;
    const int tx = tid & 15, ty = tid >> 4;
    const int row0 = blockIdx.y * 128, col0 = blockIdx.x * 128;
    const int a_r = tid >> 1, a_k = (tid & 1) * 8;
    const int b_r = tid >> 4, b_c = (tid & 15) * 8;
    float acc[8][8];
    #pragma unroll
    for (int i = 0; i < 8; i++)
        #pragma unroll
        for (int j = 0; j < 8; j++) acc[i][j] = 0.f;
    const bool aok = (row0 + a_r) < M;
    const float* Aptr = A + (size_t)(row0 + a_r) * K + a_k;
    const float* Bptr = B + (size_t)b_r * N + col0 + b_c;

    const int NKT = K / 16;
    float4 pa0, pa1, pb0, pb1;

    // preload stage 0
    pa0 = aok ? *(const float4*)(Aptr + 0) : make_float4(0.f, 0.f, 0.f, 0.f);
    pa1 = aok ? *(const float4*)(Aptr + 4) : make_float4(0.f, 0.f, 0.f, 0.f);
    pb0 = *(const float4*)(Bptr);
    pb1 = *(const float4*)(Bptr + 4);
    {
        As[0][a_k + 0][a_r] = pa0.x; As[0][a_k + 1][a_r] = pa0.y;
        As[0][a_k + 2][a_r] = pa0.z; As[0][a_k + 3][a_r] = pa0.w;
        As[0][a_k + 4][a_r] = pa1.x; As[0][a_k + 5][a_r] = pa1.y;
        As[0][a_k + 6][a_r] = pa1.z; As[0][a_k + 7][a_r] = pa1.w;
        *(float4*)&Bs[0][b_r][b_c]     = pb0;
        *(float4*)&Bs[0][b_r][b_c + 4] = pb1;
    }
    __syncthreads();

    for (int kt = 0; kt < NKT; kt++) {
        const int cur = kt & 1;
        const bool more = (kt + 1) < NKT;
        if (more) {
            const int kg = (kt + 1) * 16;
            pa0 = aok ? *(const float4*)(Aptr + kg)     : make_float4(0.f, 0.f, 0.f, 0.f);
            pa1 = aok ? *(const float4*)(Aptr + kg + 4) : make_float4(0.f, 0.f, 0.f, 0.f);
            pb0 = *(const float4*)(Bptr + (size_t)kg * N);
            pb1 = *(const float4*)(Bptr + (size_t)kg * N + 4);   // FIXED: same row, +4 cols
        }
        #pragma unroll
        for (int kk = 0; kk < 16; kk++) {
            float ar[8], br[8];
            *(float4*)&ar[0] = *(const float4*)&As[cur][kk][ty * 4];
            *(float4*)&ar[4] = *(const float4*)&As[cur][kk][64 + ty * 4];
            *(float4*)&br[0] = *(const float4*)&Bs[cur][kk][tx * 4];
            *(float4*)&br[4] = *(const float4*)&Bs[cur][kk][64 + tx * 4];
            #pragma unroll
            for (int i = 0; i < 8; i++)
                #pragma unroll
                for (int j = 0; j < 8; j++) acc[i][j] += ar[i] * br[j];
        }
        if (more) {
            const int nxt = cur ^ 1;
            As[nxt][a_k + 0][a_r] = pa0.x; As[nxt][a_k + 1][a_r] = pa0.y;
            As[nxt][a_k + 2][a_r] = pa0.z; As[nxt][a_k + 3][a_r] = pa0.w;
            As[nxt][a_k + 4][a_r] = pa1.x; As[nxt][a_k + 5][a_r] = pa1.y;
            As[nxt][a_k + 6][a_r] = pa1.z; As[nxt][a_k + 7][a_r] = pa1.w;
            *(float4*)&Bs[nxt][b_r][b_c]     = pb0;
            *(float4*)&Bs[nxt][b_r][b_c + 4] = pb1;
        }
        __syncthreads();
    }

    #pragma unroll
    for (int ig = 0; ig < 2; ig++) {
        #pragma unroll
        for (int ii = 0; ii < 4; ii++) {
            int r = row0 + ig * 64 + ty * 4 + ii;
            if (r >= M) continue;
            #pragma unroll
            for (int jg = 0; jg < 2; jg++) {
                int c = col0 + jg * 64 + tx * 4;
                float4 o;
                o.x = acc[ig * 4 + ii][jg * 4 + 0];
                o.y = acc[ig * 4 + ii][jg * 4 + 1];
                o.z = acc[ig * 4 + ii][jg * 4 + 2];
                o.w = acc[ig * 4 + ii][jg * 4 + 3];
                if (BIAS) {
                    o.x += bias[c];     o.y += bias[c + 1];
                    o.z += bias[c + 2]; o.w += bias[c + 3];
                }
                *(float4*)&C[(size_t)r * N + c] = o;
            }
        }
    }
}

// ---------------------------------------------------------------------------
// TF32 tensor-core GEMM (expert FFNs; not routing-critical) — unchanged (R8).
// ---------------------------------------------------------------------------
#define WA_STRIDE 40
#define WB_STRIDE 264
#define WA_TILE  (128 * WA_STRIDE)
#define WB_TILE  (32 * WB_STRIDE)
#define WSTAGE   (WA_TILE + WB_TILE)
#define WSMEM_BYTES (WSTAGE * 2 * 4)

template<bool RELU>
__global__ __launch_bounds__(256, 1)
void tf32_gemm_wide(const float* __restrict__ A0, const float* __restrict__ B0,
                    float* __restrict__ C0, int M, int N, int K,
                    long long sA, long long sB, long long sC) {
    extern __shared__ float sm[];
    const float* A = A0 + (long long)blockIdx.z * sA;
    const float* B = B0 + (long long)blockIdx.z * sB;
    float*       C = C0 + (long long)blockIdx.z * sC;

    const int tid  = threadIdx.x;
    const int warp = tid >> 5;
    const int lane = tid & 31;
    const int wm = (warp & 1) * 64;
    const int wn = (warp >> 1) * 64;
    const int bm = blockIdx.y * 128;
    const int bn = blockIdx.x * 256;

    const int a_r0 = tid >> 3;
    const int a_c  = (tid & 7) * 4;
    const int pbase = (a_c & 4) ? (a_c - 3) : a_c;

    const int r  = lane >> 2;
    const int cq = lane & 3;

    float acc[4][8][4];
    #pragma unroll
    for (int mt = 0; mt < 4; mt++)
        #pragma unroll
        for (int nt = 0; nt < 8; nt++)
            #pragma unroll
            for (int q = 0; q < 4; q++) acc[mt][nt][q] = 0.f;

    const int KT = K / 32;

    {
        float* As = sm;
        float* Bs = sm + WA_TILE;
        #pragma unroll
        for (int i = 0; i < 4; i++) {
            int ar = a_r0 + 32 * i;
            float4 v = *(const float4*)(A + (size_t)(bm + ar) * K + a_c);
            float* d = As + ar * WA_STRIDE + pbase;
            d[0] = tf32r(v.x); d[2] = tf32r(v.y); d[4] = tf32r(v.z); d[6] = tf32r(v.w);
        }
        #pragma unroll
        for (int j = 0; j < 8; j++) {
            int idx = tid + 256 * j;
            int brow = idx >> 6;
            int bcol = (idx & 63) * 4;
            float4 v = *(const float4*)(B + (size_t)brow * N + bn + bcol);
            float4 w;
            w.x = tf32r(v.x); w.y = tf32r(v.y); w.z = tf32r(v.z); w.w = tf32r(v.w);
            *(float4*)(Bs + brow * WB_STRIDE + bcol) = w;
        }
    }
    __syncthreads();

    for (int kt = 0; kt < KT; kt++) {
        const int cur = kt & 1;
        const float* As = sm + cur * WSTAGE;
        const float* Bs = As + WA_TILE;
        const bool more = (kt + 1) < KT;

        float4 pa[4], pb[8];
        if (more) {
            const int k0g = (kt + 1) * 32;
            #pragma unroll
            for (int i = 0; i < 4; i++)
                pa[i] = *(const float4*)(A + (size_t)(bm + a_r0 + 32 * i) * K + k0g + a_c);
            #pragma unroll
            for (int j = 0; j < 8; j++) {
                int idx = tid + 256 * j;
                int brow = idx >> 6;
                int bcol = (idx & 63) * 4;
                pb[j] = *(const float4*)(B + (size_t)(k0g + brow) * N + bn + bcol);
            }
        }

        #pragma unroll
        for (int ks = 0; ks < 4; ks++) {
            const int k0 = ks * 8;
            unsigned af[4][4];
            #pragma unroll
            for (int mt = 0; mt < 4; mt++) {
                const float* ab = As + (wm + mt * 16 + r) * WA_STRIDE + k0 + 2 * cq;
                float2 lo = *(const float2*)ab;
                float2 hi = *(const float2*)(ab + 8 * WA_STRIDE);
                af[mt][0] = __float_as_uint(lo.x);
                af[mt][1] = __float_as_uint(hi.x);
                af[mt][2] = __float_as_uint(lo.y);
                af[mt][3] = __float_as_uint(hi.y);
            }
            unsigned bf[8][2];
            #pragma unroll
            for (int nt = 0; nt < 8; nt++) {
                const float* bb = Bs + (k0 + cq) * WB_STRIDE + wn + nt * 8 + r;
                bf[nt][0] = __float_as_uint(bb[0]);
                bf[nt][1] = __float_as_uint(bb[4 * WB_STRIDE]);
            }
            #pragma unroll
            for (int mt = 0; mt < 4; mt++)
                #pragma unroll
                for (int nt = 0; nt < 8; nt++) {
                    asm volatile(
                        "mma.sync.aligned.m16n8k8.row.col.f32.tf32.tf32.f32 "
                        "{%0,%1,%2,%3}, {%4,%5,%6,%7}, {%8,%9}, {%0,%1,%2,%3};"
                        : "+f"(acc[mt][nt][0]), "+f"(acc[mt][nt][1]),
                          "+f"(acc[mt][nt][2]), "+f"(acc[mt][nt][3])
                        : "r"(af[mt][0]), "r"(af[mt][1]), "r"(af[mt][2]), "r"(af[mt][3]),
                          "r"(bf[nt][0]), "r"(bf[nt][1]));
                }
        }

        if (more) {
            float* nAs = sm + (cur ^ 1) * WSTAGE;
            float* nBs = nAs + WA_TILE;
            #pragma unroll
            for (int i = 0; i < 4; i++) {
                float* d = nAs + (a_r0 + 32 * i) * WA_STRIDE + pbase;
                d[0] = tf32r(pa[i].x); d[2] = tf32r(pa[i].y);
                d[4] = tf32r(pa[i].z); d[6] = tf32r(pa[i].w);
            }
            #pragma unroll
            for (int j = 0; j < 8; j++) {
                int idx = tid + 256 * j;
                int brow = idx >> 6;
                int bcol = (idx & 63) * 4;
                float4 w;
                w.x = tf32r(pb[j].x); w.y = tf32r(pb[j].y);
                w.z = tf32r(pb[j].z); w.w = tf32r(pb[j].w);
                *(float4*)(nBs + brow * WB_STRIDE + bcol) = w;
            }
        }
        __syncthreads();
    }

    #pragma unroll
    for (int mt = 0; mt < 4; mt++) {
        #pragma unroll
        for (int nt = 0; nt < 8; nt++) {
            int row = bm + wm + mt * 16 + r;
            int col = bn + wn + nt * 8 + 2 * cq;
            float2 v0, v1;
            v0.x = acc[mt][nt][0]; v0.y = acc[mt][nt][1];
            v1.x = acc[mt][nt][2]; v1.y = acc[mt][nt][3];
            if (RELU) {
                v0.x = fmaxf(v0.x, 0.f); v0.y = fmaxf(v0.y, 0.f);
                v1.x = fmaxf(v1.x, 0.f); v1.y = fmaxf(v1.y, 0.f);
            }
            *(float2*)&C[(size_t)row * N + col] = v0;
            *(float2*)&C[(size_t)(row + 8) * N + col] = v1;
        }
    }
}

// ---------------------------------------------------------------------------
// Init scratch (assign = -1, loss = 0)
// ---------------------------------------------------------------------------
__global__ void init_kernel() {
    int i = blockIdx.x * blockDim.x + threadIdx.x;
    if (i < NEXP * EROWS) g_assign[i] = -1;
    if (i == 0) g_loss[0] = 0.f;
}

// ---------------------------------------------------------------------------
// Fused rel-pos attention (unchanged, proven)
// ---------------------------------------------------------------------------
__global__ __launch_bounds__(256)
void attn_kernel(const float* __restrict__ u_bias, const float* __restrict__ v_bias) {
    __shared__ float qs[SEQ * DHEAD];
    __shared__ float ks[SEQ * DHEAD];
    __shared__ float vs[SEQ * DHEAD];
    __shared__ float ps[SEQ * DHEAD];
    __shared__ float pr[SEQ * SEQ];
    const int b = blockIdx.x >> 5;
    const int h = blockIdx.x & 31;
    const int tid = threadIdx.x;

    #pragma unroll
    for (int t = 0; t < 8; t++) {
        int idx = tid + t * 256;
        int s = idx >> 5, d = idx & 31;
        size_t g = ((size_t)((b * SEQ + s) * NHEAD + h)) * DHEAD + d;
        qs[idx] = g_q[g]; ks[idx] = g_k[g]; vs[idx] = g_v[g];
        ps[idx] = g_pos[(size_t)(s * NHEAD + h) * DHEAD + d];
    }
    __syncthreads();

    const int i  = tid >> 2;
    const int j0 = (tid & 3) * 16;
    float qd[32];

    #pragma unroll
    for (int d = 0; d < 32; d++) qd[d] = qs[i * 32 + d] + __ldg(&v_bias[h * 32 + d]);
    #pragma unroll
    for (int jj = 0; jj < 16; jj++) {
        int j = j0 + jj;
        float a = 0.f;
        #pragma unroll
        for (int d = 0; d < 32; d++) a += qd[d] * ps[j * 32 + d];
        pr[i * 64 + j] = a;
    }
    __syncthreads();

    float sh[16];
    #pragma unroll
    for (int jj = 0; jj < 16; jj++) {
        int c = j0 + jj;
        int f = (i + 1) * 64 + c;
        int ii = f / 65;
        int jp = f - ii * 65;
        sh[jj] = (jp == 0) ? 0.f : pr[ii * 64 + (jp - 1)];
    }
    __syncthreads();
    #pragma unroll
    for (int jj = 0; jj < 16; jj++) pr[i * 64 + j0 + jj] = sh[jj];
    __syncthreads();

    #pragma unroll
    for (int d = 0; d < 32; d++) qd[d] = qs[i * 32 + d] + __ldg(&u_bias[h * 32 + d]);
    #pragma unroll
    for (int jj = 0; jj < 16; jj++) {
        int j = j0 + jj;
        float a = 0.f;
        #pragma unroll
        for (int d = 0; d < 32; d++) a += qd[d] * ks[j * 32 + d];
        pr[i * 64 + j] = (a + pr[i * 64 + j]) * 0.03125f;
    }
    float m = -1e30f;
    #pragma unroll
    for (int jj = 0; jj < 16; jj++) m = fmaxf(m, pr[i * 64 + j0 + jj]);
    m = fmaxf(m, __shfl_xor_sync(0xFFFFFFFFu, m, 1));
    m = fmaxf(m, __shfl_xor_sync(0xFFFFFFFFu, m, 2));
    float ex[16], ssum = 0.f;
    #pragma unroll
    for (int jj = 0; jj < 16; jj++) { ex[jj] = expf(pr[i * 64 + j0 + jj] - m); ssum += ex[jj]; }
    ssum += __shfl_xor_sync(0xFFFFFFFFu, ssum, 1);
    ssum += __shfl_xor_sync(0xFFFFFFFFu, ssum, 2);
    float inv = 1.0f / ssum;
    #pragma unroll
    for (int jj = 0; jj < 16; jj++) pr[i * 64 + j0 + jj] = ex[jj] * inv;
    __syncthreads();

    const int i2 = tid >> 2;
    const int d0 = (tid & 3) * 8;
    float o[8] = {0.f, 0.f, 0.f, 0.f, 0.f, 0.f, 0.f, 0.f};
    for (int j = 0; j < 64; j++) {
        float aw = pr[i2 * 64 + j];
        #pragma unroll
        for (int dd = 0; dd < 8; dd++) o[dd] += aw * vs[j * 32 + d0 + dd];
    }
    size_t gbase = ((size_t)((b * SEQ + i2) * NHEAD + h)) * DHEAD + d0;
    #pragma unroll
    for (int dd = 0; dd < 8; dd++) g_ctx[gbase + dd] = o[dd];
}

// ---------------------------------------------------------------------------
// LN1 (unchanged)
// ---------------------------------------------------------------------------
__global__ __launch_bounds__(256)
void ln1_kernel(const float* __restrict__ x, const float* __restrict__ gma,
                const float* __restrict__ bta) {
    int row = blockIdx.x, tid = threadIdx.x;
    const float* pa = g_a + (size_t)row * DIM;
    const float* pr = x   + (size_t)row * DIM;
    float vals[4], s = 0.f;
    #pragma unroll
    for (int t = 0; t < 4; t++) {
        int c = tid + t * 256;
        float v = pa[c] + pr[c];
        vals[t] = v; s += v;
    }
    s = blockReduceSum(s);
    float mu = s * (1.f / DIM);
    float vsum = 0.f;
    #pragma unroll
    for (int t = 0; t < 4; t++) { float d = vals[t] - mu; vsum += d * d; }
    vsum = blockReduceSum(vsum);
    float rstd = rsqrtf(vsum * (1.f / DIM) + 1e-5f);
    #pragma unroll
    for (int t = 0; t < 4; t++) {
        int c = tid + t * 256;
        g_x1[(size_t)row * DIM + c] = (vals[t] - mu) * rstd * gma[c] + bta[c];
    }
}

// ---------------------------------------------------------------------------
// Gating (unchanged)
// ---------------------------------------------------------------------------
__global__ __launch_bounds__(256)
void gating_kernel(const float* __restrict__ wg) {
    int warp = (blockIdx.x * blockDim.x + threadIdx.x) >> 5;
    int lane = threadIdx.x & 31;
    if (warp >= NTOK) return;
    const float* xr = g_x1 + (size_t)warp * DIM;
    float a0 = 0.f, a1 = 0.f, a2 = 0.f, a3 = 0.f;
    for (int d = lane; d < DIM; d += 32) {
        float xv = xr[d];
        float4 w = ((const float4*)wg)[d];
        a0 += xv * w.x; a1 += xv * w.y; a2 += xv * w.z; a3 += xv * w.w;
    }
    #pragma unroll
    for (int o = 16; o; o >>= 1) {
        a0 += __shfl_down_sync(0xFFFFFFFFu, a0, o);
        a1 += __shfl_down_sync(0xFFFFFFFFu, a1, o);
        a2 += __shfl_down_sync(0xFFFFFFFFu, a2, o);
        a3 += __shfl_down_sync(0xFFFFFFFFu, a3, o);
    }
    if (lane == 0) {
        float m = fmaxf(fmaxf(a0, a1), fmaxf(a2, a3));
        float e0 = expf(a0 - m), e1 = expf(a1 - m), e2 = expf(a2 - m), e3 = expf(a3 - m);
        float s = e0 + e1 + e2 + e3;
        g_raw[warp * 4 + 0] = e0 / s;
        g_raw[warp * 4 + 1] = e1 / s;
        g_raw[warp * 4 + 2] = e2 / s;
        g_raw[warp * 4 + 3] = e3 / s;
    }
}

// ---------------------------------------------------------------------------
// Routing (unchanged)
// ---------------------------------------------------------------------------
__global__ void routing_kernel() {
    if (threadIdx.x != 0) return;
    int b = blockIdx.x;
    int cnt1[4] = {0, 0, 0, 0};
    float dens[4] = {0.f, 0.f, 0.f, 0.f};
    float proxy[4] = {0.f, 0.f, 0.f, 0.f};
    int e2a[64]; float g2a[64]; bool k2a[64];

    for (int n = 0; n < SEQ; n++) {
        int tok = b * SEQ + n;
        float rr[4];
        #pragma unroll
        for (int e = 0; e < 4; e++) { rr[e] = g_raw[tok * 4 + e]; proxy[e] += rr[e]; }
        int e1 = 0; float g1 = rr[0];
        #pragma unroll
        for (int e = 1; e < 4; e++) if (rr[e] > g1) { g1 = rr[e]; e1 = e; }
        int e2 = -1; float g2 = -1.f;
        #pragma unroll
        for (int e = 0; e < 4; e++) {
            if (e == e1) continue;
            if (rr[e] > g2) { g2 = rr[e]; e2 = e; }
        }
        dens[e1] += 1.f;
        float denom = g1 + g2 + 1e-9f;
        float g1n = g1 / denom, g2n = g2 / denom;
        int p1 = cnt1[e1]++;
        g_sE1[tok] = e1;
        if (p1 < CAP) {
            g_sP1[tok] = p1; g_sG1[tok] = g1n;
            g_assign[(e1 * BATCH + b) * CAP + p1] = tok;
        } else {
            g_sP1[tok] = -1; g_sG1[tok] = 0.f;
        }
        float u = jax_uniform_token(tok);
        k2a[n] = (u < g2n / 0.2f);
        e2a[n] = e2; g2a[n] = g2n;
    }
    int c1c[4];
    #pragma unroll
    for (int e = 0; e < 4; e++) c1c[e] = cnt1[e] < CAP ? cnt1[e] : CAP;
    int cnt2[4] = {0, 0, 0, 0};
    for (int n = 0; n < SEQ; n++) {
        int tok = b * SEQ + n;
        g_sE2[tok] = e2a[n];
        g_sP2[tok] = -1; g_sG2[tok] = 0.f;
        if (k2a[n]) {
            int e2 = e2a[n];
            int p2 = cnt2[e2] + c1c[e2];
            cnt2[e2]++;
            if (p2 < CAP) {
                g_sP2[tok] = p2; g_sG2[tok] = g2a[n];
                g_assign[(e2 * BATCH + b) * CAP + p2] = tok;
            }
        }
    }
    float part = 0.f;
    #pragma unroll
    for (int e = 0; e < 4; e++) part += (proxy[e] * (1.f / SEQ)) * (dens[e] * (1.f / SEQ));
    atomicAdd(&g_loss[0], part);
}

// ---------------------------------------------------------------------------
// Gather dispatched tokens into expert input rows (zero for empty slots)
// ---------------------------------------------------------------------------
__global__ __launch_bounds__(256)
void gather_kernel() {
    int row = blockIdx.x;
    int tok = g_assign[row];
    float4* dst = ((float4*)g_ei) + (size_t)row * 256;
    if (tok >= 0) {
        const float4* src = ((const float4*)g_x1) + (size_t)tok * 256;
        dst[threadIdx.x] = src[threadIdx.x];
    } else {
        dst[threadIdx.x] = make_float4(0.f, 0.f, 0.f, 0.f);
    }
}

// ---------------------------------------------------------------------------
// Combine + residual + LN2 (unchanged)
// ---------------------------------------------------------------------------
__global__ __launch_bounds__(256)
void combine_ln2_kernel(const float* __restrict__ gma, const float* __restrict__ bta,
                        float* __restrict__ out, int out_size) {
    int tok = blockIdx.x, tid = threadIdx.x;
    int b = tok >> 6;
    int p1 = g_sP1[tok], p2 = g_sP2[tok];
    float g1 = g_sG1[tok], g2 = g_sG2[tok];
    const float* r1 = (p1 >= 0) ? g_eo + ((size_t)g_sE1[tok] * EROWS + b * CAP + p1) * DIM : nullptr;
    const float* r2 = (p2 >= 0) ? g_eo + ((size_t)g_sE2[tok] * EROWS + b * CAP + p2) * DIM : nullptr;
    const float* xr = g_x1 + (size_t)tok * DIM;
    float vals[4], s = 0.f;
    #pragma unroll
    for (int t = 0; t < 4; t++) {
        int c = tid + t * 256;
        float y = 0.f;
        if (r1) y += g1 * r1[c];
        if (r2) y += g2 * r2[c];
        float v = y + xr[c];
        vals[t] = v; s += v;
    }
    s = blockReduceSum(s);
    float mu = s * (1.f / DIM);
    float vsum = 0.f;
    #pragma unroll
    for (int t = 0; t < 4; t++) { float d = vals[t] - mu; vsum += d * d; }
    vsum = blockReduceSum(vsum);
    float rstd = rsqrtf(vsum * (1.f / DIM) + 1e-5f);
    #pragma unroll
    for (int t = 0; t < 4; t++) {
        int c = tid + t * 256;
        out[(size_t)tok * DIM + c] = (vals[t] - mu) * rstd * gma[c] + bta[c];
    }
    if (tok == 0 && tid == 0 && out_size > NTOK * DIM) {
        out[(size_t)NTOK * DIM] = g_loss[0] * ((float)(NEXP * NEXP) * 0.01f / (float)(BATCH * NEXP));
    }
}

// ---------------------------------------------------------------------------
// Host side
// ---------------------------------------------------------------------------
static void launch_gemm(const float* A, const float* B, const float* bias, float* C,
                        int M, int N, int K, bool biasF) {
    dim3 grid(N / 128, (M + 127) / 128);
    if (biasF) sgemm_kernel<true ><<<grid, 256>>>(A, B, bias, C, M, N, K);
    else       sgemm_kernel<false><<<grid, 256>>>(A, B, bias, C, M, N, K);
}

extern "C" void kernel_launch(void* const* d_in, const int* in_sizes, int n_in,
                              void* d_out, int out_size) {
    const float* x       = (const float*)d_in[0];
    const float* pos_enc = (const float*)d_in[1];
    const float* Wq      = (const float*)d_in[2];
    const float* bq      = (const float*)d_in[3];
    const float* Wk      = (const float*)d_in[4];
    const float* bk      = (const float*)d_in[5];
    const float* Wv      = (const float*)d_in[6];
    const float* bv      = (const float*)d_in[7];
    const float* Wpos    = (const float*)d_in[8];
    const float* u_bias  = (const float*)d_in[9];
    const float* v_bias  = (const float*)d_in[10];
    const float* Wo      = (const float*)d_in[11];
    const float* bo      = (const float*)d_in[12];
    const float* ln1_g   = (const float*)d_in[13];
    const float* ln1_b   = (const float*)d_in[14];
    const float* ln2_g   = (const float*)d_in[15];
    const float* ln2_b   = (const float*)d_in[16];
    const float* wg      = (const float*)d_in[17];
    const float* w1      = (const float*)d_in[18];
    const float* w2      = (const float*)d_in[19];
    float* out = (float*)d_out;

    float *q, *k, *v, *ctx, *a, *pos, *ei, *hid, *eo;
    cudaGetSymbolAddress((void**)&q,   g_q);
    cudaGetSymbolAddress((void**)&k,   g_k);
    cudaGetSymbolAddress((void**)&v,   g_v);
    cudaGetSymbolAddress((void**)&ctx, g_ctx);
    cudaGetSymbolAddress((void**)&a,   g_a);
    cudaGetSymbolAddress((void**)&pos, g_pos);
    cudaGetSymbolAddress((void**)&ei,  g_ei);
    cudaGetSymbolAddress((void**)&hid, g_hid);
    cudaGetSymbolAddress((void**)&eo,  g_eo);

    static bool attr_done = false;
    if (!attr_done) {
        cudaFuncSetAttribute(tf32_gemm_wide<true>,
                             cudaFuncAttributeMaxDynamicSharedMemorySize, WSMEM_BYTES);
        cudaFuncSetAttribute(tf32_gemm_wide<false>,
                             cudaFuncAttributeMaxDynamicSharedMemorySize, WSMEM_BYTES);
        attr_done = true;
    }

    init_kernel<<<128, 256>>>();

    // Projections (routing-critical: exact fp32, bit-compatible accumulation)
    launch_gemm(x, Wq, bq, q, NTOK, DIM, DIM, true);
    launch_gemm(x, Wk, bk, k, NTOK, DIM, DIM, true);
    launch_gemm(x, Wv, bv, v, NTOK, DIM, DIM, true);
    launch_gemm(pos_enc, Wpos, nullptr, pos, SEQ, DIM, DIM, false);

    attn_kernel<<<BATCH * NHEAD, 256>>>(u_bias, v_bias);

    launch_gemm(ctx, Wo, bo, a, NTOK, DIM, DIM, true);
    ln1_kernel<<<NTOK, 256>>>(x, ln1_g, ln1_b);

    gating_kernel<<<(NTOK * 32 + 255) / 256, 256>>>(wg);
    routing_kernel<<<BATCH, 32>>>();
    gather_kernel<<<NEXP * EROWS, 256>>>();

    // Expert FFNs on TF32 tensor cores (NOT routing-critical)
    {
        dim3 g1d(HID / 256, EROWS / 128, NEXP);
        tf32_gemm_wide<true><<<g1d, 256, WSMEM_BYTES>>>(
            ei, w1, hid, EROWS, HID, DIM,
            (long long)EROWS * DIM, (long long)DIM * HID, (long long)EROWS * HID);
        dim3 g2d(DIM / 256, EROWS / 128, NEXP);
        tf32_gemm_wide<false><<<g2d, 256, WSMEM_BYTES>>>(
            hid, w2, eo, EROWS, DIM, HID,
            (long long)EROWS * HID, (long long)HID * DIM, (long long)EROWS * DIM);
    }

    combine_ln2_kernel<<<NTOK, 256>>>(ln2_g, ln2_b, out, out_size);
}

// round 15
// speedup vs baseline: 2.9083x; 1.1265x over previous
#include <cuda_runtime.h>
#include <cuda_fp16.h>
#include <cstdint>

// ---------------------------------------------------------------------------
// Problem constants
// ---------------------------------------------------------------------------
#define BATCH 256
#define SEQ   64
#define DIM   1024
#define NHEAD 32
#define DHEAD 32
#define NEXP  4
#define HID   1536
#define CAP   32
#define NTOK  (BATCH*SEQ)            // 16384
#define EROWS (BATCH*CAP)            // 8192 rows per expert

// ---------------------------------------------------------------------------
// Scratch (device globals; no allocation allowed)
// ---------------------------------------------------------------------------
__device__ float g_q  [NTOK*DIM];
__device__ float g_k  [NTOK*DIM];
__device__ float g_v  [NTOK*DIM];
__device__ float g_ctx[NTOK*DIM];
__device__ float g_a  [NTOK*DIM];
__device__ float g_x1 [NTOK*DIM];
__device__ float g_pos[SEQ*DIM];
__device__ float g_raw[NTOK*NEXP];
__device__ int   g_assign[NEXP*EROWS];
__device__ int   g_sE1[NTOK]; __device__ int g_sP1[NTOK]; __device__ float g_sG1[NTOK];
__device__ int   g_sE2[NTOK]; __device__ int g_sP2[NTOK]; __device__ float g_sG2[NTOK];
__device__ float g_eo [NEXP*EROWS*DIM];
__device__ float g_loss[1];
// fp16 expert-path buffers
__device__ __half g_w1t[NEXP*HID*DIM];   // [E][N=HID][K=DIM]
__device__ __half g_w2t[NEXP*DIM*HID];   // [E][N=DIM][K=HID]
__device__ __half g_eih[NEXP*EROWS*DIM];
__device__ __half g_hidh[NEXP*EROWS*HID];

// ---------------------------------------------------------------------------
// Helpers
// ---------------------------------------------------------------------------
__device__ __forceinline__ float blockReduceSum(float v) {
    __shared__ float sh[8];
    __shared__ float tot;
    int lane = threadIdx.x & 31, wid = threadIdx.x >> 5;
    #pragma unroll
    for (int o = 16; o; o >>= 1) v += __shfl_down_sync(0xFFFFFFFFu, v, o);
    if (lane == 0) sh[wid] = v;
    __syncthreads();
    if (wid == 0) {
        v = (lane < 8) ? sh[lane] : 0.f;
        #pragma unroll
        for (int o = 4; o; o >>= 1) v += __shfl_down_sync(0xFFFFFFFFu, v, o);
        if (lane == 0) tot = v;
    }
    __syncthreads();
    return tot;
}

// ---------------------------------------------------------------------------
// Threefry2x32, PARTITIONABLE path (verified PASS R5/R6/R8/R13).
// ---------------------------------------------------------------------------
#define TF_ROT(x0, x1, r)  { x0 += x1; x1 = ((x1 << (r)) | (x1 >> (32 - (r)))); x1 ^= x0; }
__device__ float jax_uniform_token(int j) {
    const unsigned KS0 = 0u;
    const unsigned KS1 = 1234u;
    const unsigned KS2 = 0x1BD11F08u;
    unsigned x0 = 0u;
    unsigned x1 = (unsigned)j;
    x0 += KS0; x1 += KS1;
    TF_ROT(x0, x1, 13) TF_ROT(x0, x1, 15) TF_ROT(x0, x1, 26) TF_ROT(x0, x1, 6)
    x0 += KS1; x1 += KS2 + 1u;
    TF_ROT(x0, x1, 17) TF_ROT(x0, x1, 29) TF_ROT(x0, x1, 16) TF_ROT(x0, x1, 24)
    x0 += KS2; x1 += KS0 + 2u;
    TF_ROT(x0, x1, 13) TF_ROT(x0, x1, 15) TF_ROT(x0, x1, 26) TF_ROT(x0, x1, 6)
    x0 += KS0; x1 += KS1 + 3u;
    TF_ROT(x0, x1, 17) TF_ROT(x0, x1, 29) TF_ROT(x0, x1, 16) TF_ROT(x0, x1, 24)
    x0 += KS1; x1 += KS2 + 4u;
    TF_ROT(x0, x1, 13) TF_ROT(x0, x1, 15) TF_ROT(x0, x1, 26) TF_ROT(x0, x1, 6)
    x0 += KS2; x1 += KS0 + 5u;
    unsigned bits = x0 ^ x1;
    unsigned f = (bits >> 9) | 0x3f800000u;
    return __uint_as_float(f) - 1.0f;
}

// ---------------------------------------------------------------------------
// fp32 SGEMM (routing-critical: QKV/pos/Wo) — unchanged from R13 (proven).
// ---------------------------------------------------------------------------
template<bool BIAS>
__global__ __launch_bounds__(256, 2)
void sgemm_kernel(const float* __restrict__ A, const float* __restrict__ B,
                  const float* __restrict__ bias, float* __restrict__ C,
                  int M, int N, int K) {
    __shared__ float As[2][16][128];
    __shared__ float Bs[2][16][128];
    const int tid = threadIdx.x;
    const int tx = tid & 15, ty = tid >> 4;
    const int row0 = blockIdx.y * 128, col0 = blockIdx.x * 128;
    const int a_r = tid >> 1, a_k = (tid & 1) * 8;
    const int b_r = tid >> 4, b_c = (tid & 15) * 8;
    float acc[8][8];
    #pragma unroll
    for (int i = 0; i < 8; i++)
        #pragma unroll
        for (int j = 0; j < 8; j++) acc[i][j] = 0.f;
    const bool aok = (row0 + a_r) < M;
    const float* Aptr = A + (size_t)(row0 + a_r) * K + a_k;
    const float* Bptr = B + (size_t)b_r * N + col0 + b_c;

    const int NKT = K / 16;
    float4 pa0, pa1, pb0, pb1;

    pa0 = aok ? *(const float4*)(Aptr + 0) : make_float4(0.f, 0.f, 0.f, 0.f);
    pa1 = aok ? *(const float4*)(Aptr + 4) : make_float4(0.f, 0.f, 0.f, 0.f);
    pb0 = *(const float4*)(Bptr);
    pb1 = *(const float4*)(Bptr + 4);
    {
        As[0][a_k + 0][a_r] = pa0.x; As[0][a_k + 1][a_r] = pa0.y;
        As[0][a_k + 2][a_r] = pa0.z; As[0][a_k + 3][a_r] = pa0.w;
        As[0][a_k + 4][a_r] = pa1.x; As[0][a_k + 5][a_r] = pa1.y;
        As[0][a_k + 6][a_r] = pa1.z; As[0][a_k + 7][a_r] = pa1.w;
        *(float4*)&Bs[0][b_r][b_c]     = pb0;
        *(float4*)&Bs[0][b_r][b_c + 4] = pb1;
    }
    __syncthreads();

    for (int kt = 0; kt < NKT; kt++) {
        const int cur = kt & 1;
        const bool more = (kt + 1) < NKT;
        if (more) {
            const int kg = (kt + 1) * 16;
            pa0 = aok ? *(const float4*)(Aptr + kg)     : make_float4(0.f, 0.f, 0.f, 0.f);
            pa1 = aok ? *(const float4*)(Aptr + kg + 4) : make_float4(0.f, 0.f, 0.f, 0.f);
            pb0 = *(const float4*)(Bptr + (size_t)kg * N);
            pb1 = *(const float4*)(Bptr + (size_t)kg * N + 4);
        }
        #pragma unroll
        for (int kk = 0; kk < 16; kk++) {
            float ar[8], br[8];
            *(float4*)&ar[0] = *(const float4*)&As[cur][kk][ty * 4];
            *(float4*)&ar[4] = *(const float4*)&As[cur][kk][64 + ty * 4];
            *(float4*)&br[0] = *(const float4*)&Bs[cur][kk][tx * 4];
            *(float4*)&br[4] = *(const float4*)&Bs[cur][kk][64 + tx * 4];
            #pragma unroll
            for (int i = 0; i < 8; i++)
                #pragma unroll
                for (int j = 0; j < 8; j++) acc[i][j] += ar[i] * br[j];
        }
        if (more) {
            const int nxt = cur ^ 1;
            As[nxt][a_k + 0][a_r] = pa0.x; As[nxt][a_k + 1][a_r] = pa0.y;
            As[nxt][a_k + 2][a_r] = pa0.z; As[nxt][a_k + 3][a_r] = pa0.w;
            As[nxt][a_k + 4][a_r] = pa1.x; As[nxt][a_k + 5][a_r] = pa1.y;
            As[nxt][a_k + 6][a_r] = pa1.z; As[nxt][a_k + 7][a_r] = pa1.w;
            *(float4*)&Bs[nxt][b_r][b_c]     = pb0;
            *(float4*)&Bs[nxt][b_r][b_c + 4] = pb1;
        }
        __syncthreads();
    }

    #pragma unroll
    for (int ig = 0; ig < 2; ig++) {
        #pragma unroll
        for (int ii = 0; ii < 4; ii++) {
            int r = row0 + ig * 64 + ty * 4 + ii;
            if (r >= M) continue;
            #pragma unroll
            for (int jg = 0; jg < 2; jg++) {
                int c = col0 + jg * 64 + tx * 4;
                float4 o;
                o.x = acc[ig * 4 + ii][jg * 4 + 0];
                o.y = acc[ig * 4 + ii][jg * 4 + 1];
                o.z = acc[ig * 4 + ii][jg * 4 + 2];
                o.w = acc[ig * 4 + ii][jg * 4 + 3];
                if (BIAS) {
                    o.x += bias[c];     o.y += bias[c + 1];
                    o.z += bias[c + 2]; o.w += bias[c + 3];
                }
                *(float4*)&C[(size_t)r * N + c] = o;
            }
        }
    }
}

// ---------------------------------------------------------------------------
// Weight transpose + fp16 convert: W[E][K][N] fp32 -> T[E][N][K] half
// ---------------------------------------------------------------------------
__global__ void transpose_half_kernel(const float* __restrict__ W,
                                      __half* __restrict__ T, int K, int N) {
    __shared__ float tile[32][33];
    const float* Wb = W + (size_t)blockIdx.z * K * N;
    __half* Tb = T + (size_t)blockIdx.z * K * N;
    int n0 = blockIdx.x * 32, k0 = blockIdx.y * 32;
    int tx = threadIdx.x, ty = threadIdx.y;     // 32 x 8
    #pragma unroll
    for (int i = 0; i < 32; i += 8)
        tile[ty + i][tx] = Wb[(size_t)(k0 + ty + i) * N + n0 + tx];
    __syncthreads();
    #pragma unroll
    for (int i = 0; i < 32; i += 8) {
        int nn = ty + i;
        Tb[(size_t)(n0 + nn) * K + k0 + tx] = __float2half(tile[tx][nn]);
    }
}

// ---------------------------------------------------------------------------
// fp16 tensor-core GEMM (expert FFNs): C[M,N] = A[M,K] @ B[N,K]^T
// A, B half row-major (K fast). mma.sync.m16n8k16.f32.f16.f16.f32.
// Block tile 128x256, K chunk 32 (2 mma k-steps), double-buffered.
// smem word stride 36 per row -> (4r+cq) mod 32 all-distinct banks.
// HALF_OUT: relu + half2 out (Ch); else fp32 float2 out (Cf).
// ---------------------------------------------------------------------------
#define HROW_W 36                         // uint words per smem row
#define HA_TILE (128 * HROW_W)            // 4608 words
#define HB_TILE (256 * HROW_W)            // 9216 words
#define HSTAGE  (HA_TILE + HB_TILE)       // 13824 words
#define HSMEM_BYTES (HSTAGE * 2 * 4)      // 110592 B

template<bool HALF_OUT>
__global__ __launch_bounds__(256, 1)
void fp16_gemm_wide(const __half* __restrict__ A0, const __half* __restrict__ B0,
                    __half* __restrict__ Ch0, float* __restrict__ Cf0,
                    int M, int N, int K,
                    long long sA, long long sB, long long sC) {
    extern __shared__ unsigned hsm[];
    const __half* A = A0 + (long long)blockIdx.z * sA;
    const __half* B = B0 + (long long)blockIdx.z * sB;

    const int tid  = threadIdx.x;
    const int warp = tid >> 5;
    const int lane = tid & 31;
    const int wm = (warp & 1) * 64;
    const int wn = (warp >> 1) * 64;       // 0,64,128,192
    const int bm = blockIdx.y * 128;
    const int bn = blockIdx.x * 256;
    const int r  = lane >> 2;              // 0..7
    const int cq = lane & 3;               // 0..3

    float acc[4][8][4];
    #pragma unroll
    for (int mt = 0; mt < 4; mt++)
        #pragma unroll
        for (int nt = 0; nt < 8; nt++)
            #pragma unroll
            for (int q = 0; q < 4; q++) acc[mt][nt][q] = 0.f;

    const int KT = K / 32;

    // Shared address math for A loads (2 uint4/thread) and B loads (4 uint4/thread)
    // A: idx = tid + 256*i, row = idx>>2 (0..127), wq = (idx&3)*4 (word offset)
    // B: idx = tid + 256*i, row = idx>>2 (0..255), wq = (idx&3)*4
    auto a_src = [&](int kc0, int i) -> const uint4* {
        int idx = tid + 256 * i; int row = idx >> 2, wq = (idx & 3) * 4;
        return (const uint4*)(A + (size_t)(bm + row) * K + kc0 + wq * 2);
    };
    auto a_dst = [&](unsigned* stage, int i) -> uint4* {
        int idx = tid + 256 * i; int row = idx >> 2, wq = (idx & 3) * 4;
        return (uint4*)(stage + row * HROW_W + wq);
    };
    auto b_src = [&](int kc0, int i) -> const uint4* {
        int idx = tid + 256 * i; int row = idx >> 2, wq = (idx & 3) * 4;
        return (const uint4*)(B + (size_t)(bn + row) * K + kc0 + wq * 2);
    };
    auto b_dst = [&](unsigned* stage, int i) -> uint4* {
        int idx = tid + 256 * i; int row = idx >> 2, wq = (idx & 3) * 4;
        return (uint4*)(stage + HA_TILE + row * HROW_W + wq);
    };

    // preload chunk 0
    {
        unsigned* st = hsm;
        #pragma unroll
        for (int i = 0; i < 2; i++) *a_dst(st, i) = *a_src(0, i);
        #pragma unroll
        for (int i = 0; i < 4; i++) *b_dst(st, i) = *b_src(0, i);
    }
    __syncthreads();

    for (int kt = 0; kt < KT; kt++) {
        const int cur = kt & 1;
        const unsigned* As = hsm + cur * HSTAGE;
        const unsigned* Bs = As + HA_TILE;
        const bool more = (kt + 1) < KT;

        uint4 pa[2], pb[4];
        if (more) {
            const int kc0 = (kt + 1) * 32;
            #pragma unroll
            for (int i = 0; i < 2; i++) pa[i] = *a_src(kc0, i);
            #pragma unroll
            for (int i = 0; i < 4; i++) pb[i] = *b_src(kc0, i);
        }

        #pragma unroll
        for (int ks = 0; ks < 2; ks++) {
            const int k0w = ks * 8;
            unsigned af[4][4];
            #pragma unroll
            for (int mt = 0; mt < 4; mt++) {
                const unsigned* ab = As + (wm + mt * 16 + r) * HROW_W + k0w + cq;
                af[mt][0] = ab[0];
                af[mt][1] = ab[8 * HROW_W];
                af[mt][2] = ab[4];
                af[mt][3] = ab[8 * HROW_W + 4];
            }
            unsigned bf[8][2];
            #pragma unroll
            for (int nt = 0; nt < 8; nt++) {
                const unsigned* bb = Bs + (wn + nt * 8 + r) * HROW_W + k0w + cq;
                bf[nt][0] = bb[0];
                bf[nt][1] = bb[4];
            }
            #pragma unroll
            for (int mt = 0; mt < 4; mt++)
                #pragma unroll
                for (int nt = 0; nt < 8; nt++) {
                    asm volatile(
                        "mma.sync.aligned.m16n8k16.row.col.f32.f16.f16.f32 "
                        "{%0,%1,%2,%3}, {%4,%5,%6,%7}, {%8,%9}, {%0,%1,%2,%3};"
                        : "+f"(acc[mt][nt][0]), "+f"(acc[mt][nt][1]),
                          "+f"(acc[mt][nt][2]), "+f"(acc[mt][nt][3])
                        : "r"(af[mt][0]), "r"(af[mt][1]), "r"(af[mt][2]), "r"(af[mt][3]),
                          "r"(bf[nt][0]), "r"(bf[nt][1]));
                }
        }

        if (more) {
            unsigned* st = hsm + (cur ^ 1) * HSTAGE;
            #pragma unroll
            for (int i = 0; i < 2; i++) *a_dst(st, i) = pa[i];
            #pragma unroll
            for (int i = 0; i < 4; i++) *b_dst(st - HA_TILE + HA_TILE, i) = pb[i];  // b_dst adds HA_TILE itself
        }
        __syncthreads();
    }

    // epilogue
    #pragma unroll
    for (int mt = 0; mt < 4; mt++) {
        #pragma unroll
        for (int nt = 0; nt < 8; nt++) {
            int row = bm + wm + mt * 16 + r;
            int col = bn + wn + nt * 8 + 2 * cq;
            if (HALF_OUT) {
                float v0 = fmaxf(acc[mt][nt][0], 0.f), v1 = fmaxf(acc[mt][nt][1], 0.f);
                float v2 = fmaxf(acc[mt][nt][2], 0.f), v3 = fmaxf(acc[mt][nt][3], 0.f);
                __half2 p0 = __floats2half2_rn(v0, v1);
                __half2 p1 = __floats2half2_rn(v2, v3);
                *(__half2*)(Ch0 + (size_t)blockIdx.z * sC + (size_t)row * N + col) = p0;
                *(__half2*)(Ch0 + (size_t)blockIdx.z * sC + (size_t)(row + 8) * N + col) = p1;
            } else {
                *(float2*)(Cf0 + (size_t)blockIdx.z * sC + (size_t)row * N + col) =
                    make_float2(acc[mt][nt][0], acc[mt][nt][1]);
                *(float2*)(Cf0 + (size_t)blockIdx.z * sC + (size_t)(row + 8) * N + col) =
                    make_float2(acc[mt][nt][2], acc[mt][nt][3]);
            }
        }
    }
}

// ---------------------------------------------------------------------------
// Init scratch (assign = -1, loss = 0)
// ---------------------------------------------------------------------------
__global__ void init_kernel() {
    int i = blockIdx.x * blockDim.x + threadIdx.x;
    if (i < NEXP * EROWS) g_assign[i] = -1;
    if (i == 0) g_loss[0] = 0.f;
}

// ---------------------------------------------------------------------------
// Fused rel-pos attention (unchanged, proven)
// ---------------------------------------------------------------------------
__global__ __launch_bounds__(256)
void attn_kernel(const float* __restrict__ u_bias, const float* __restrict__ v_bias) {
    __shared__ float qs[SEQ * DHEAD];
    __shared__ float ks[SEQ * DHEAD];
    __shared__ float vs[SEQ * DHEAD];
    __shared__ float ps[SEQ * DHEAD];
    __shared__ float pr[SEQ * SEQ];
    const int b = blockIdx.x >> 5;
    const int h = blockIdx.x & 31;
    const int tid = threadIdx.x;

    #pragma unroll
    for (int t = 0; t < 8; t++) {
        int idx = tid + t * 256;
        int s = idx >> 5, d = idx & 31;
        size_t g = ((size_t)((b * SEQ + s) * NHEAD + h)) * DHEAD + d;
        qs[idx] = g_q[g]; ks[idx] = g_k[g]; vs[idx] = g_v[g];
        ps[idx] = g_pos[(size_t)(s * NHEAD + h) * DHEAD + d];
    }
    __syncthreads();

    const int i  = tid >> 2;
    const int j0 = (tid & 3) * 16;
    float qd[32];

    #pragma unroll
    for (int d = 0; d < 32; d++) qd[d] = qs[i * 32 + d] + __ldg(&v_bias[h * 32 + d]);
    #pragma unroll
    for (int jj = 0; jj < 16; jj++) {
        int j = j0 + jj;
        float a = 0.f;
        #pragma unroll
        for (int d = 0; d < 32; d++) a += qd[d] * ps[j * 32 + d];
        pr[i * 64 + j] = a;
    }
    __syncthreads();

    float sh[16];
    #pragma unroll
    for (int jj = 0; jj < 16; jj++) {
        int c = j0 + jj;
        int f = (i + 1) * 64 + c;
        int ii = f / 65;
        int jp = f - ii * 65;
        sh[jj] = (jp == 0) ? 0.f : pr[ii * 64 + (jp - 1)];
    }
    __syncthreads();
    #pragma unroll
    for (int jj = 0; jj < 16; jj++) pr[i * 64 + j0 + jj] = sh[jj];
    __syncthreads();

    #pragma unroll
    for (int d = 0; d < 32; d++) qd[d] = qs[i * 32 + d] + __ldg(&u_bias[h * 32 + d]);
    #pragma unroll
    for (int jj = 0; jj < 16; jj++) {
        int j = j0 + jj;
        float a = 0.f;
        #pragma unroll
        for (int d = 0; d < 32; d++) a += qd[d] * ks[j * 32 + d];
        pr[i * 64 + j] = (a + pr[i * 64 + j]) * 0.03125f;
    }
    float m = -1e30f;
    #pragma unroll
    for (int jj = 0; jj < 16; jj++) m = fmaxf(m, pr[i * 64 + j0 + jj]);
    m = fmaxf(m, __shfl_xor_sync(0xFFFFFFFFu, m, 1));
    m = fmaxf(m, __shfl_xor_sync(0xFFFFFFFFu, m, 2));
    float ex[16], ssum = 0.f;
    #pragma unroll
    for (int jj = 0; jj < 16; jj++) { ex[jj] = expf(pr[i * 64 + j0 + jj] - m); ssum += ex[jj]; }
    ssum += __shfl_xor_sync(0xFFFFFFFFu, ssum, 1);
    ssum += __shfl_xor_sync(0xFFFFFFFFu, ssum, 2);
    float inv = 1.0f / ssum;
    #pragma unroll
    for (int jj = 0; jj < 16; jj++) pr[i * 64 + j0 + jj] = ex[jj] * inv;
    __syncthreads();

    const int i2 = tid >> 2;
    const int d0 = (tid & 3) * 8;
    float o[8] = {0.f, 0.f, 0.f, 0.f, 0.f, 0.f, 0.f, 0.f};
    for (int j = 0; j < 64; j++) {
        float aw = pr[i2 * 64 + j];
        #pragma unroll
        for (int dd = 0; dd < 8; dd++) o[dd] += aw * vs[j * 32 + d0 + dd];
    }
    size_t gbase = ((size_t)((b * SEQ + i2) * NHEAD + h)) * DHEAD + d0;
    #pragma unroll
    for (int dd = 0; dd < 8; dd++) g_ctx[gbase + dd] = o[dd];
}

// ---------------------------------------------------------------------------
// LN1 (unchanged)
// ---------------------------------------------------------------------------
__global__ __launch_bounds__(256)
void ln1_kernel(const float* __restrict__ x, const float* __restrict__ gma,
                const float* __restrict__ bta) {
    int row = blockIdx.x, tid = threadIdx.x;
    const float* pa = g_a + (size_t)row * DIM;
    const float* pr = x   + (size_t)row * DIM;
    float vals[4], s = 0.f;
    #pragma unroll
    for (int t = 0; t < 4; t++) {
        int c = tid + t * 256;
        float v = pa[c] + pr[c];
        vals[t] = v; s += v;
    }
    s = blockReduceSum(s);
    float mu = s * (1.f / DIM);
    float vsum = 0.f;
    #pragma unroll
    for (int t = 0; t < 4; t++) { float d = vals[t] - mu; vsum += d * d; }
    vsum = blockReduceSum(vsum);
    float rstd = rsqrtf(vsum * (1.f / DIM) + 1e-5f);
    #pragma unroll
    for (int t = 0; t < 4; t++) {
        int c = tid + t * 256;
        g_x1[(size_t)row * DIM + c] = (vals[t] - mu) * rstd * gma[c] + bta[c];
    }
}

// ---------------------------------------------------------------------------
// Gating (unchanged)
// ---------------------------------------------------------------------------
__global__ __launch_bounds__(256)
void gating_kernel(const float* __restrict__ wg) {
    int warp = (blockIdx.x * blockDim.x + threadIdx.x) >> 5;
    int lane = threadIdx.x & 31;
    if (warp >= NTOK) return;
    const float* xr = g_x1 + (size_t)warp * DIM;
    float a0 = 0.f, a1 = 0.f, a2 = 0.f, a3 = 0.f;
    for (int d = lane; d < DIM; d += 32) {
        float xv = xr[d];
        float4 w = ((const float4*)wg)[d];
        a0 += xv * w.x; a1 += xv * w.y; a2 += xv * w.z; a3 += xv * w.w;
    }
    #pragma unroll
    for (int o = 16; o; o >>= 1) {
        a0 += __shfl_down_sync(0xFFFFFFFFu, a0, o);
        a1 += __shfl_down_sync(0xFFFFFFFFu, a1, o);
        a2 += __shfl_down_sync(0xFFFFFFFFu, a2, o);
        a3 += __shfl_down_sync(0xFFFFFFFFu, a3, o);
    }
    if (lane == 0) {
        float m = fmaxf(fmaxf(a0, a1), fmaxf(a2, a3));
        float e0 = expf(a0 - m), e1 = expf(a1 - m), e2 = expf(a2 - m), e3 = expf(a3 - m);
        float s = e0 + e1 + e2 + e3;
        g_raw[warp * 4 + 0] = e0 / s;
        g_raw[warp * 4 + 1] = e1 / s;
        g_raw[warp * 4 + 2] = e2 / s;
        g_raw[warp * 4 + 3] = e3 / s;
    }
}

// ---------------------------------------------------------------------------
// Routing (unchanged)
// ---------------------------------------------------------------------------
__global__ void routing_kernel() {
    if (threadIdx.x != 0) return;
    int b = blockIdx.x;
    int cnt1[4] = {0, 0, 0, 0};
    float dens[4] = {0.f, 0.f, 0.f, 0.f};
    float proxy[4] = {0.f, 0.f, 0.f, 0.f};
    int e2a[64]; float g2a[64]; bool k2a[64];

    for (int n = 0; n < SEQ; n++) {
        int tok = b * SEQ + n;
        float rr[4];
        #pragma unroll
        for (int e = 0; e < 4; e++) { rr[e] = g_raw[tok * 4 + e]; proxy[e] += rr[e]; }
        int e1 = 0; float g1 = rr[0];
        #pragma unroll
        for (int e = 1; e < 4; e++) if (rr[e] > g1) { g1 = rr[e]; e1 = e; }
        int e2 = -1; float g2 = -1.f;
        #pragma unroll
        for (int e = 0; e < 4; e++) {
            if (e == e1) continue;
            if (rr[e] > g2) { g2 = rr[e]; e2 = e; }
        }
        dens[e1] += 1.f;
        float denom = g1 + g2 + 1e-9f;
        float g1n = g1 / denom, g2n = g2 / denom;
        int p1 = cnt1[e1]++;
        g_sE1[tok] = e1;
        if (p1 < CAP) {
            g_sP1[tok] = p1; g_sG1[tok] = g1n;
            g_assign[(e1 * BATCH + b) * CAP + p1] = tok;
        } else {
            g_sP1[tok] = -1; g_sG1[tok] = 0.f;
        }
        float u = jax_uniform_token(tok);
        k2a[n] = (u < g2n / 0.2f);
        e2a[n] = e2; g2a[n] = g2n;
    }
    int c1c[4];
    #pragma unroll
    for (int e = 0; e < 4; e++) c1c[e] = cnt1[e] < CAP ? cnt1[e] : CAP;
    int cnt2[4] = {0, 0, 0, 0};
    for (int n = 0; n < SEQ; n++) {
        int tok = b * SEQ + n;
        g_sE2[tok] = e2a[n];
        g_sP2[tok] = -1; g_sG2[tok] = 0.f;
        if (k2a[n]) {
            int e2 = e2a[n];
            int p2 = cnt2[e2] + c1c[e2];
            cnt2[e2]++;
            if (p2 < CAP) {
                g_sP2[tok] = p2; g_sG2[tok] = g2a[n];
                g_assign[(e2 * BATCH + b) * CAP + p2] = tok;
            }
        }
    }
    float part = 0.f;
    #pragma unroll
    for (int e = 0; e < 4; e++) part += (proxy[e] * (1.f / SEQ)) * (dens[e] * (1.f / SEQ));
    atomicAdd(&g_loss[0], part);
}

// ---------------------------------------------------------------------------
// Gather + fp16 convert: expert input rows (zeros for empty slots)
// ---------------------------------------------------------------------------
__global__ __launch_bounds__(256)
void gather_half_kernel() {
    int row = blockIdx.x;               // 0 .. NEXP*EROWS-1
    int tok = g_assign[row];
    int c = threadIdx.x * 4;
    __half2 p0 = __floats2half2_rn(0.f, 0.f), p1 = p0;
    if (tok >= 0) {
        float4 v = *((const float4*)(g_x1 + (size_t)tok * DIM + c));
        p0 = __floats2half2_rn(v.x, v.y);
        p1 = __floats2half2_rn(v.z, v.w);
    }
    __half2* dst = (__half2*)(g_eih + (size_t)row * DIM + c);
    dst[0] = p0; dst[1] = p1;
}

// ---------------------------------------------------------------------------
// Combine + residual + LN2 (unchanged)
// ---------------------------------------------------------------------------
__global__ __launch_bounds__(256)
void combine_ln2_kernel(const float* __restrict__ gma, const float* __restrict__ bta,
                        float* __restrict__ out, int out_size) {
    int tok = blockIdx.x, tid = threadIdx.x;
    int b = tok >> 6;
    int p1 = g_sP1[tok], p2 = g_sP2[tok];
    float g1 = g_sG1[tok], g2 = g_sG2[tok];
    const float* r1 = (p1 >= 0) ? g_eo + ((size_t)g_sE1[tok] * EROWS + b * CAP + p1) * DIM : nullptr;
    const float* r2 = (p2 >= 0) ? g_eo + ((size_t)g_sE2[tok] * EROWS + b * CAP + p2) * DIM : nullptr;
    const float* xr = g_x1 + (size_t)tok * DIM;
    float vals[4], s = 0.f;
    #pragma unroll
    for (int t = 0; t < 4; t++) {
        int c = tid + t * 256;
        float y = 0.f;
        if (r1) y += g1 * r1[c];
        if (r2) y += g2 * r2[c];
        float v = y + xr[c];
        vals[t] = v; s += v;
    }
    s = blockReduceSum(s);
    float mu = s * (1.f / DIM);
    float vsum = 0.f;
    #pragma unroll
    for (int t = 0; t < 4; t++) { float d = vals[t] - mu; vsum += d * d; }
    vsum = blockReduceSum(vsum);
    float rstd = rsqrtf(vsum * (1.f / DIM) + 1e-5f);
    #pragma unroll
    for (int t = 0; t < 4; t++) {
        int c = tid + t * 256;
        out[(size_t)tok * DIM + c] = (vals[t] - mu) * rstd * gma[c] + bta[c];
    }
    if (tok == 0 && tid == 0 && out_size > NTOK * DIM) {
        out[(size_t)NTOK * DIM] = g_loss[0] * ((float)(NEXP * NEXP) * 0.01f / (float)(BATCH * NEXP));
    }
}

// ---------------------------------------------------------------------------
// Host side
// ---------------------------------------------------------------------------
static void launch_gemm(const float* A, const float* B, const float* bias, float* C,
                        int M, int N, int K, bool biasF) {
    dim3 grid(N / 128, (M + 127) / 128);
    if (biasF) sgemm_kernel<true ><<<grid, 256>>>(A, B, bias, C, M, N, K);
    else       sgemm_kernel<false><<<grid, 256>>>(A, B, bias, C, M, N, K);
}

extern "C" void kernel_launch(void* const* d_in, const int* in_sizes, int n_in,
                              void* d_out, int out_size) {
    const float* x       = (const float*)d_in[0];
    const float* pos_enc = (const float*)d_in[1];
    const float* Wq      = (const float*)d_in[2];
    const float* bq      = (const float*)d_in[3];
    const float* Wk      = (const float*)d_in[4];
    const float* bk      = (const float*)d_in[5];
    const float* Wv      = (const float*)d_in[6];
    const float* bv      = (const float*)d_in[7];
    const float* Wpos    = (const float*)d_in[8];
    const float* u_bias  = (const float*)d_in[9];
    const float* v_bias  = (const float*)d_in[10];
    const float* Wo      = (const float*)d_in[11];
    const float* bo      = (const float*)d_in[12];
    const float* ln1_g   = (const float*)d_in[13];
    const float* ln1_b   = (const float*)d_in[14];
    const float* ln2_g   = (const float*)d_in[15];
    const float* ln2_b   = (const float*)d_in[16];
    const float* wg      = (const float*)d_in[17];
    const float* w1      = (const float*)d_in[18];
    const float* w2      = (const float*)d_in[19];
    float* out = (float*)d_out;

    float *q, *k, *v, *ctx, *a, *pos, *eo;
    __half *w1t, *w2t, *eih, *hidh;
    cudaGetSymbolAddress((void**)&q,    g_q);
    cudaGetSymbolAddress((void**)&k,    g_k);
    cudaGetSymbolAddress((void**)&v,    g_v);
    cudaGetSymbolAddress((void**)&ctx,  g_ctx);
    cudaGetSymbolAddress((void**)&a,    g_a);
    cudaGetSymbolAddress((void**)&pos,  g_pos);
    cudaGetSymbolAddress((void**)&eo,   g_eo);
    cudaGetSymbolAddress((void**)&w1t,  g_w1t);
    cudaGetSymbolAddress((void**)&w2t,  g_w2t);
    cudaGetSymbolAddress((void**)&eih,  g_eih);
    cudaGetSymbolAddress((void**)&hidh, g_hidh);

    static bool attr_done = false;
    if (!attr_done) {
        cudaFuncSetAttribute(fp16_gemm_wide<true>,
                             cudaFuncAttributeMaxDynamicSharedMemorySize, HSMEM_BYTES);
        cudaFuncSetAttribute(fp16_gemm_wide<false>,
                             cudaFuncAttributeMaxDynamicSharedMemorySize, HSMEM_BYTES);
        attr_done = true;
    }

    init_kernel<<<128, 256>>>();

    // Weight transpose + fp16 convert (w1: K=DIM,N=HID ; w2: K=HID,N=DIM)
    {
        dim3 blk(32, 8);
        transpose_half_kernel<<<dim3(HID / 32, DIM / 32, NEXP), blk>>>(w1, w1t, DIM, HID);
        transpose_half_kernel<<<dim3(DIM / 32, HID / 32, NEXP), blk>>>(w2, w2t, HID, DIM);
    }

    // Projections (routing-critical: exact fp32, bit-compatible accumulation)
    launch_gemm(x, Wq, bq, q, NTOK, DIM, DIM, true);
    launch_gemm(x, Wk, bk, k, NTOK, DIM, DIM, true);
    launch_gemm(x, Wv, bv, v, NTOK, DIM, DIM, true);
    launch_gemm(pos_enc, Wpos, nullptr, pos, SEQ, DIM, DIM, false);

    attn_kernel<<<BATCH * NHEAD, 256>>>(u_bias, v_bias);

    launch_gemm(ctx, Wo, bo, a, NTOK, DIM, DIM, true);
    ln1_kernel<<<NTOK, 256>>>(x, ln1_g, ln1_b);

    gating_kernel<<<(NTOK * 32 + 255) / 256, 256>>>(wg);
    routing_kernel<<<BATCH, 32>>>();
    gather_half_kernel<<<NEXP * EROWS, 256>>>();

    // Expert FFNs: fp16 m16n8k16 (2x FLOP/instr vs tf32 m16n8k8)
    fp16_gemm_wide<true><<<dim3(HID / 256, EROWS / 128, NEXP), 256, HSMEM_BYTES>>>(
        eih, w1t, hidh, nullptr, EROWS, HID, DIM,
        (long long)EROWS * DIM, (long long)HID * DIM, (long long)EROWS * HID);
    fp16_gemm_wide<false><<<dim3(DIM / 256, EROWS / 128, NEXP), 256, HSMEM_BYTES>>>(
        hidh, w2t, nullptr, eo, EROWS, DIM, HID,
        (long long)EROWS * HID, (long long)DIM * HID, (long long)EROWS * DIM);

    combine_ln2_kernel<<<NTOK, 256>>>(ln2_g, ln2_b, out, out_size);
}